// round 2
// baseline (speedup 1.0000x reference)
#include <cuda_runtime.h>
#include <math.h>

#define B_  8
#define T_  2048
#define NE_ 384
#define HQ_ 8
#define HKV_ 2
#define D_  48
#define GROUP_ 4
#define MROWS (B_*T_)
#define HALF_D (D_/2)

// Scratch (device globals; no allocations allowed)
__device__ float g_q[(size_t)B_*HQ_*T_*D_];    // [B,HQ,T,D]
__device__ float g_k[(size_t)B_*HKV_*T_*D_];   // [B,HKV,T,D]
__device__ float g_v[(size_t)B_*HKV_*T_*D_];   // [B,HKV,T,D]
__device__ float g_o[(size_t)B_*T_*NE_];       // [B,T,NE] attention output
__device__ float g_cos[T_*HALF_D];
__device__ float g_sin[T_*HALF_D];

// ---------------------------------------------------------------------------
// RoPE table: match jax fp32 angle computation, then accurate double trig.
// ---------------------------------------------------------------------------
__global__ void rope_table_kernel() {
    int idx = blockIdx.x * blockDim.x + threadIdx.x;
    if (idx >= T_ * HALF_D) return;
    int t = idx / HALF_D, p = idx % HALF_D;
    float inv = 1.0f / powf(10000.0f, (2.0f * (float)p) / 48.0f);
    float ang = (float)t * inv;           // fp32 rounding like the reference
    g_cos[idx] = (float)cos((double)ang); // accurate trig of that angle
    g_sin[idx] = (float)sin((double)ang);
}

// ---------------------------------------------------------------------------
// RoPE apply (interleaved pairs). WHICH==0 -> q (64 head-rows), 1 -> k (16).
// ---------------------------------------------------------------------------
template<int WHICH>
__global__ void rope_apply_kernel() {
    float* buf = (WHICH == 0) ? g_q : g_k;
    const int NH = (WHICH == 0) ? (B_*HQ_) : (B_*HKV_);
    int idx = blockIdx.x * blockDim.x + threadIdx.x;
    int total = NH * T_ * HALF_D;
    if (idx >= total) return;
    int p = idx % HALF_D;
    int t = (idx / HALF_D) % T_;
    size_t base = (size_t)(idx / HALF_D) * D_;  // (x*T + t)*D
    float c = g_cos[t*HALF_D + p];
    float s = g_sin[t*HALF_D + p];
    float e = buf[base + 2*p];
    float o = buf[base + 2*p + 1];
    buf[base + 2*p]     = e*c - o*s;
    buf[base + 2*p + 1] = e*s + o*c;
}

// ---------------------------------------------------------------------------
// Tiled fp32 GEMM, 64x64 tiles, BK=16, 256 threads, 4x4 microtile.
// MODE 0: x@wq  -> scatter to g_q [B,HQ,T,D]
// MODE 1: x@wk  -> scatter to g_k [B,HKV,T,D]
// MODE 2: x@wv  -> scatter to g_v
// MODE 3: g_o@wo + bias -> Cout row-major [M,N]
// K is always NE_=384, M always 16384 (multiple of 64).
// ---------------------------------------------------------------------------
template<int MODE>
__global__ __launch_bounds__(256) void gemm_kernel(
    const float* __restrict__ A_in, const float* __restrict__ W,
    float* __restrict__ Cout, const float* __restrict__ bias, int N)
{
    const int K = NE_;
    const float* A = (MODE == 3) ? (const float*)g_o : A_in;
    __shared__ float As[16][65];
    __shared__ float Bs[16][65];
    int bm = blockIdx.y * 64;
    int bn = blockIdx.x * 64;
    int tid = threadIdx.x;
    int tx = tid & 15, ty = tid >> 4;
    float acc[4][4];
    #pragma unroll
    for (int i = 0; i < 4; i++)
        #pragma unroll
        for (int j = 0; j < 4; j++) acc[i][j] = 0.f;

    for (int k0 = 0; k0 < K; k0 += 16) {
        #pragma unroll
        for (int i = tid; i < 1024; i += 256) {
            int r = i >> 4, c = i & 15;
            As[c][r] = A[(size_t)(bm + r) * K + k0 + c];
        }
        #pragma unroll
        for (int i = tid; i < 1024; i += 256) {
            int r = i >> 6, c = i & 63;
            int col = bn + c;
            Bs[r][c] = (col < N) ? W[(size_t)(k0 + r) * N + col] : 0.f;
        }
        __syncthreads();
        #pragma unroll
        for (int kk = 0; kk < 16; kk++) {
            float a[4], bw[4];
            #pragma unroll
            for (int i = 0; i < 4; i++) a[i] = As[kk][ty*4 + i];
            #pragma unroll
            for (int j = 0; j < 4; j++) bw[j] = Bs[kk][tx*4 + j];
            #pragma unroll
            for (int i = 0; i < 4; i++)
                #pragma unroll
                for (int j = 0; j < 4; j++)
                    acc[i][j] = fmaf(a[i], bw[j], acc[i][j]);
        }
        __syncthreads();
    }

    #pragma unroll
    for (int i = 0; i < 4; i++) {
        int row = bm + ty*4 + i;
        #pragma unroll
        for (int j = 0; j < 4; j++) {
            int col = bn + tx*4 + j;
            if (col >= N) continue;
            float val = acc[i][j];
            if (MODE == 0) {
                int bb = row / T_, t = row % T_;
                int h = col / D_, d = col % D_;
                g_q[(((size_t)bb*HQ_ + h)*T_ + t)*D_ + d] = val;
            } else if (MODE == 1) {
                int bb = row / T_, t = row % T_;
                int h = col / D_, d = col % D_;
                g_k[(((size_t)bb*HKV_ + h)*T_ + t)*D_ + d] = val;
            } else if (MODE == 2) {
                int bb = row / T_, t = row % T_;
                int h = col / D_, d = col % D_;
                g_v[(((size_t)bb*HKV_ + h)*T_ + t)*D_ + d] = val;
            } else {
                Cout[(size_t)row * N + col] = val + bias[col];
            }
        }
    }
}

// ---------------------------------------------------------------------------
// Flash attention, fp32. Grid: (T/64, B*HQ). 256 threads.
// Q tile 64x48 in smem; K and V share one smem buffer (static-smem budget).
// Online softmax with 4 threads/row.
// ---------------------------------------------------------------------------
__global__ __launch_bounds__(256) void attn_kernel() {
    __shared__ float Qs[64][49];
    __shared__ float KV[64][49];
    __shared__ float Ss[64][65];
    __shared__ float row_m[64], row_l[64], row_sc[64];

    int bh = blockIdx.y;
    int b  = bh / HQ_, h = bh % HQ_, hk = h / GROUP_;
    int m0 = blockIdx.x * 64;
    int tid = threadIdx.x;
    int tx = tid & 15, ty = tid >> 4;

    const float* Qp = g_q + (((size_t)b*HQ_ + h)*T_ + m0) * D_;
    const float* Kp = g_k + (((size_t)b*HKV_ + hk)*T_) * D_;
    const float* Vp = g_v + (((size_t)b*HKV_ + hk)*T_) * D_;

    const float scale = 0.14433756729740643f; // 1/sqrt(48)
    for (int i = tid; i < 64*D_; i += 256) Qs[i / D_][i % D_] = Qp[i] * scale;
    if (tid < 64) { row_m[tid] = -3.0e38f; row_l[tid] = 0.f; }

    float oacc[4][3];
    #pragma unroll
    for (int i = 0; i < 4; i++)
        #pragma unroll
        for (int j = 0; j < 3; j++) oacc[i][j] = 0.f;

    int ntiles = blockIdx.x + 1;
    for (int tile = 0; tile < ntiles; tile++) {
        __syncthreads();  // (a) prev PV done; Q/init visible on first iter
        const float* Kt = Kp + (size_t)tile * 64 * D_;
        for (int i = tid; i < 64*D_; i += 256) KV[i / D_][i % D_] = Kt[i];
        __syncthreads();  // (b)

        float sacc[4][4];
        #pragma unroll
        for (int i = 0; i < 4; i++)
            #pragma unroll
            for (int j = 0; j < 4; j++) sacc[i][j] = 0.f;
        #pragma unroll 8
        for (int kk = 0; kk < D_; kk++) {
            float a[4], kb[4];
            #pragma unroll
            for (int i = 0; i < 4; i++) a[i] = Qs[ty*4 + i][kk];
            #pragma unroll
            for (int j = 0; j < 4; j++) kb[j] = KV[tx*4 + j][kk];
            #pragma unroll
            for (int i = 0; i < 4; i++)
                #pragma unroll
                for (int j = 0; j < 4; j++)
                    sacc[i][j] = fmaf(a[i], kb[j], sacc[i][j]);
        }
        if (tile == blockIdx.x) {   // diagonal tile: causal mask
            #pragma unroll
            for (int i = 0; i < 4; i++)
                #pragma unroll
                for (int j = 0; j < 4; j++) {
                    int qr = ty*4 + i, kc = tx*4 + j;
                    Ss[qr][kc] = (kc <= qr) ? sacc[i][j] : -1.0e30f;
                }
        } else {
            #pragma unroll
            for (int i = 0; i < 4; i++)
                #pragma unroll
                for (int j = 0; j < 4; j++)
                    Ss[ty*4 + i][tx*4 + j] = sacc[i][j];
        }
        __syncthreads();  // (c) S done; K dead

        // Load V into the shared KV buffer (starts global loads early)
        const float* Vt = Vp + (size_t)tile * 64 * D_;
        for (int i = tid; i < 64*D_; i += 256) KV[i / D_][i % D_] = Vt[i];

        // Online softmax: 4 threads per row
        int row = tid >> 2, l4 = tid & 3;
        float mx = -3.0e38f;
        #pragma unroll
        for (int k = 0; k < 16; k++) mx = fmaxf(mx, Ss[row][l4 + 4*k]);
        mx = fmaxf(mx, __shfl_xor_sync(0xffffffffu, mx, 1));
        mx = fmaxf(mx, __shfl_xor_sync(0xffffffffu, mx, 2));
        float oldm = row_m[row];
        float newm = fmaxf(oldm, mx);
        float lsum = 0.f;
        #pragma unroll
        for (int k = 0; k < 16; k++) {
            int c = l4 + 4*k;
            float pv = expf(Ss[row][c] - newm);
            Ss[row][c] = pv;
            lsum += pv;
        }
        lsum += __shfl_xor_sync(0xffffffffu, lsum, 1);
        lsum += __shfl_xor_sync(0xffffffffu, lsum, 2);
        if (l4 == 0) {
            float sc = expf(oldm - newm);
            row_sc[row] = sc;
            row_l[row]  = row_l[row] * sc + lsum;
            row_m[row]  = newm;
        }
        __syncthreads();  // (d) P, V, row_sc ready

        #pragma unroll
        for (int i = 0; i < 4; i++) {
            float sc = row_sc[ty*4 + i];
            #pragma unroll
            for (int j = 0; j < 3; j++) oacc[i][j] *= sc;
        }
        #pragma unroll 8
        for (int s = 0; s < 64; s++) {
            float pr[4], vv[3];
            #pragma unroll
            for (int i = 0; i < 4; i++) pr[i] = Ss[ty*4 + i][s];
            #pragma unroll
            for (int j = 0; j < 3; j++) vv[j] = KV[s][tx*3 + j];
            #pragma unroll
            for (int i = 0; i < 4; i++)
                #pragma unroll
                for (int j = 0; j < 3; j++)
                    oacc[i][j] = fmaf(pr[i], vv[j], oacc[i][j]);
        }
    }

    // Final normalize + write to [B,T,NE] layout for the out-proj GEMM
    float* Op = g_o + ((size_t)b*T_ + m0)*NE_ + h*D_;
    #pragma unroll
    for (int i = 0; i < 4; i++) {
        int r = ty*4 + i;
        float inv = 1.0f / row_l[r];
        #pragma unroll
        for (int j = 0; j < 3; j++)
            Op[(size_t)r*NE_ + tx*3 + j] = oacc[i][j] * inv;
    }
}

// ---------------------------------------------------------------------------
extern "C" void kernel_launch(void* const* d_in, const int* in_sizes, int n_in,
                              void* d_out, int out_size)
{
    const float* x  = (const float*)d_in[0];
    const float* wq = (const float*)d_in[1];
    const float* wk = (const float*)d_in[2];
    const float* wv = (const float*)d_in[3];
    const float* wo = (const float*)d_in[4];
    const float* bo = (const float*)d_in[5];
    float* out = (float*)d_out;

    // RoPE table
    rope_table_kernel<<<(T_*HALF_D + 255)/256, 256>>>();

    // QKV projections (scatter to head-major layouts)
    gemm_kernel<0><<<dim3(NE_/64, MROWS/64), 256>>>(x, wq, nullptr, nullptr, HQ_*D_);
    gemm_kernel<1><<<dim3(2,      MROWS/64), 256>>>(x, wk, nullptr, nullptr, HKV_*D_);
    gemm_kernel<2><<<dim3(2,      MROWS/64), 256>>>(x, wv, nullptr, nullptr, HKV_*D_);

    // RoPE
    {
        int nq = B_*HQ_*T_*HALF_D;
        int nk = B_*HKV_*T_*HALF_D;
        rope_apply_kernel<0><<<(nq + 255)/256, 256>>>();
        rope_apply_kernel<1><<<(nk + 255)/256, 256>>>();
    }

    // Flash attention
    attn_kernel<<<dim3(T_/64, B_*HQ_), 256>>>();

    // Output projection + bias
    gemm_kernel<3><<<dim3(NE_/64, MROWS/64), 256>>>(nullptr, wo, out, bo, NE_);
}

// round 3
// speedup vs baseline: 2.5498x; 2.5498x over previous
#include <cuda_runtime.h>
#include <math.h>
#include <stdint.h>

#define B_  8
#define T_  2048
#define NE_ 384
#define HQ_ 8
#define HKV_ 2
#define D_  48
#define MROWS (B_*T_)
#define HALF_D 24

// Scratch (device globals; no allocations allowed)
__device__ float g_q[(size_t)B_*HQ_*T_*D_];    // [B,HQ,T,D]  (rope applied)
__device__ float g_k[(size_t)B_*HKV_*T_*D_];   // [B,HKV,T,D] (rope applied)
__device__ float g_v[(size_t)B_*HKV_*T_*D_];   // [B,HKV,T,D]
__device__ float g_o[(size_t)B_*T_*NE_];       // [B,T,NE] attention output
__device__ float g_cos[T_*HALF_D];
__device__ float g_sin[T_*HALF_D];

// ---------------------------------------------------------------------------
__device__ __forceinline__ uint32_t f2tf(float x) {
    uint32_t u;
    asm("cvt.rna.tf32.f32 %0, %1;" : "=r"(u) : "f"(x));
    return u;
}

__device__ __forceinline__ void mma8(float& d0, float& d1, float& d2, float& d3,
                                     uint32_t a0, uint32_t a1, uint32_t a2, uint32_t a3,
                                     uint32_t b0, uint32_t b1) {
    asm volatile("mma.sync.aligned.m16n8k8.row.col.f32.tf32.tf32.f32 "
                 "{%0,%1,%2,%3},{%4,%5,%6,%7},{%8,%9},{%0,%1,%2,%3};"
                 : "+f"(d0), "+f"(d1), "+f"(d2), "+f"(d3)
                 : "r"(a0), "r"(a1), "r"(a2), "r"(a3), "r"(b0), "r"(b1));
}

// ---------------------------------------------------------------------------
// RoPE table: fp32 angle (matches jax), accurate double trig.
// ---------------------------------------------------------------------------
__global__ void rope_table_kernel() {
    int idx = blockIdx.x * blockDim.x + threadIdx.x;
    if (idx >= T_ * HALF_D) return;
    int t = idx / HALF_D, p = idx % HALF_D;
    float inv = 1.0f / powf(10000.0f, (2.0f * (float)p) / 48.0f);
    float ang = (float)t * inv;
    g_cos[idx] = (float)cos((double)ang);
    g_sin[idx] = (float)sin((double)ang);
}

// ---------------------------------------------------------------------------
// TF32 tensor-core GEMM.
// MODE 0: fused QKV:  A=x [16384,384], B=[wq|wk|wv] logical [384,576],
//         epilogue applies RoPE to q/k and scatters to g_q/g_k/g_v head-major.
// MODE 1: out-proj:   A=g_o [16384,384], B=wo [384,384], +bias -> Cout.
// Block tile 128x64, 8 warps as 4(M) x 2(N), warp tile 32x32, BK=16.
// ---------------------------------------------------------------------------
template<int MODE>
__global__ __launch_bounds__(256) void gemm_tc(
    const float* __restrict__ A_in, const float* __restrict__ wq,
    const float* __restrict__ wk, const float* __restrict__ wv,
    const float* __restrict__ bias, float* __restrict__ Cout)
{
    __shared__ uint32_t As[128][20];   // [m][k], pad 20 -> conflict-free frag reads
    __shared__ uint32_t Bs[16][72];    // [k][n], pad 72 -> conflict-free frag reads

    const float* A = (MODE == 0) ? A_in : (const float*)g_o;
    int tid  = threadIdx.x;
    int lane = tid & 31, wid = tid >> 5;
    int wm = wid & 3, wn = wid >> 2;          // 4 x 2 warp grid
    int group = lane >> 2, tid4 = lane & 3;
    int bm = blockIdx.y * 128;
    int bn = blockIdx.x * 64;

    float acc[2][4][4];
    #pragma unroll
    for (int mt = 0; mt < 2; mt++)
        #pragma unroll
        for (int nt = 0; nt < 4; nt++)
            #pragma unroll
            for (int r = 0; r < 4; r++) acc[mt][nt][r] = 0.f;

    for (int k0 = 0; k0 < NE_; k0 += 16) {
        // Load A tile (128x16) as float4, convert to tf32
        #pragma unroll
        for (int i = tid; i < 512; i += 256) {
            int r = i >> 2, kq = (i & 3) * 4;
            float4 v = *(const float4*)&A[(size_t)(bm + r) * NE_ + k0 + kq];
            As[r][kq + 0] = f2tf(v.x);
            As[r][kq + 1] = f2tf(v.y);
            As[r][kq + 2] = f2tf(v.z);
            As[r][kq + 3] = f2tf(v.w);
        }
        // Load B tile (16x64) with 3-source selection (MODE 0) or wo (MODE 1)
        #pragma unroll
        for (int i = tid; i < 1024; i += 256) {
            int r = i >> 6, c = i & 63;
            int col = bn + c;
            float w;
            if (MODE == 1) {
                w = wq[(size_t)(k0 + r) * 384 + col];
            } else {
                if (col < 384)      w = wq[(size_t)(k0 + r) * 384 + col];
                else if (col < 480) w = wk[(size_t)(k0 + r) * 96 + col - 384];
                else                w = wv[(size_t)(k0 + r) * 96 + col - 480];
            }
            Bs[r][c] = f2tf(w);
        }
        __syncthreads();

        #pragma unroll
        for (int ks = 0; ks < 2; ks++) {
            uint32_t af[2][4], bf[4][2];
            #pragma unroll
            for (int mt = 0; mt < 2; mt++) {
                int row = wm * 32 + mt * 16 + group;
                af[mt][0] = As[row][ks * 8 + tid4];
                af[mt][1] = As[row + 8][ks * 8 + tid4];
                af[mt][2] = As[row][ks * 8 + tid4 + 4];
                af[mt][3] = As[row + 8][ks * 8 + tid4 + 4];
            }
            #pragma unroll
            for (int nt = 0; nt < 4; nt++) {
                int nn = wn * 32 + nt * 8 + group;
                bf[nt][0] = Bs[ks * 8 + tid4][nn];
                bf[nt][1] = Bs[ks * 8 + tid4 + 4][nn];
            }
            #pragma unroll
            for (int mt = 0; mt < 2; mt++)
                #pragma unroll
                for (int nt = 0; nt < 4; nt++)
                    mma8(acc[mt][nt][0], acc[mt][nt][1], acc[mt][nt][2], acc[mt][nt][3],
                         af[mt][0], af[mt][1], af[mt][2], af[mt][3],
                         bf[nt][0], bf[nt][1]);
        }
        __syncthreads();
    }

    // Epilogue: accumulator holds adjacent col pairs (RoPE pairs).
    #pragma unroll
    for (int mt = 0; mt < 2; mt++) {
        #pragma unroll
        for (int nt = 0; nt < 4; nt++) {
            int col = bn + wn * 32 + nt * 8 + tid4 * 2;
            #pragma unroll
            for (int half = 0; half < 2; half++) {
                int row = bm + wm * 32 + mt * 16 + group + half * 8;
                float e = acc[mt][nt][half * 2 + 0];
                float o = acc[mt][nt][half * 2 + 1];
                if (MODE == 1) {
                    Cout[(size_t)row * 384 + col]     = e + bias[col];
                    Cout[(size_t)row * 384 + col + 1] = o + bias[col + 1];
                } else {
                    int b = row >> 11, t = row & 2047;
                    if (col < 480) {   // q or k: apply RoPE
                        int lc = (col < 384) ? col : col - 384;
                        int h = lc / 48, d = lc % 48, p = d >> 1;
                        float cc = g_cos[t * 24 + p], ss = g_sin[t * 24 + p];
                        float re = e * cc - o * ss;
                        float ro = e * ss + o * cc;
                        if (col < 384) {
                            size_t base = (((size_t)b * 8 + h) * 2048 + t) * 48 + d;
                            g_q[base] = re; g_q[base + 1] = ro;
                        } else {
                            size_t base = (((size_t)b * 2 + h) * 2048 + t) * 48 + d;
                            g_k[base] = re; g_k[base + 1] = ro;
                        }
                    } else {           // v: direct
                        int lc = col - 480;
                        int h = lc / 48, d = lc % 48;
                        size_t base = (((size_t)b * 2 + h) * 2048 + t) * 48 + d;
                        g_v[base] = e; g_v[base + 1] = o;
                    }
                }
            }
        }
    }
}

// ---------------------------------------------------------------------------
// Flash attention with TF32 tensor cores.
// Grid (T/64, B*HQ), 256 threads = 8 warps as 4(M) x 2(N).
// QK: S(64x64) = Q(64x48) @ K^T ; PV: O(64x48) = P(64x64) @ V.
// Q fragments live in registers; K/V/P in smem with conflict-free pads.
// ---------------------------------------------------------------------------
__global__ __launch_bounds__(256) void attn_tc() {
    __shared__ uint32_t Ks[64][52];   // [kvrow][d] tf32 bits
    __shared__ uint32_t Vs[64][56];   // [kvrow][d] tf32 bits
    __shared__ uint32_t Ps[64][68];   // [qrow][s]  tf32 bits (also Q staging)
    __shared__ float row_m[64], row_l[64];
    __shared__ float rmax_p[2][64], rsum_p[2][64];

    int tid = threadIdx.x, lane = tid & 31, wid = tid >> 5;
    int wm = wid & 3, wn = wid >> 2;
    int group = lane >> 2, tid4 = lane & 3;
    int bh = blockIdx.y, b = bh >> 3, h = bh & 7, hk = h >> 2;
    int m0 = blockIdx.x * 64;

    const float* Qp = g_q + (((size_t)b * 8 + h) * 2048 + m0) * 48;
    const float* Kp = g_k + ((size_t)b * 2 + hk) * 2048 * 48;
    const float* Vp = g_v + ((size_t)b * 2 + hk) * 2048 * 48;

    // Stage Q (scaled, tf32) through Ps, then pull fragments into registers.
    const float scale = 0.14433756729740643f;  // 1/sqrt(48)
    for (int i = tid; i < 768; i += 256) {
        int r = i / 12, dq = (i % 12) * 4;
        float4 v = *(const float4*)&Qp[r * 48 + dq];
        Ps[r][dq + 0] = f2tf(v.x * scale);
        Ps[r][dq + 1] = f2tf(v.y * scale);
        Ps[r][dq + 2] = f2tf(v.z * scale);
        Ps[r][dq + 3] = f2tf(v.w * scale);
    }
    if (tid < 64) { row_m[tid] = -3.0e38f; row_l[tid] = 0.f; }
    __syncthreads();

    int r0 = wm * 16 + group, r1 = r0 + 8;
    uint32_t qf[6][4];
    #pragma unroll
    for (int ks = 0; ks < 6; ks++) {
        qf[ks][0] = Ps[r0][ks * 8 + tid4];
        qf[ks][1] = Ps[r1][ks * 8 + tid4];
        qf[ks][2] = Ps[r0][ks * 8 + tid4 + 4];
        qf[ks][3] = Ps[r1][ks * 8 + tid4 + 4];
    }

    float oacc[3][4];
    #pragma unroll
    for (int nt = 0; nt < 3; nt++)
        #pragma unroll
        for (int r = 0; r < 4; r++) oacc[nt][r] = 0.f;

    int ntiles = blockIdx.x + 1;
    for (int tile = 0; tile < ntiles; tile++) {
        __syncthreads();  // (A) prior PV reads + Q frag reads complete
        const float* Kt = Kp + (size_t)tile * 64 * 48;
        const float* Vt = Vp + (size_t)tile * 64 * 48;
        for (int i = tid; i < 768; i += 256) {
            int r = i / 12, dq = (i % 12) * 4;
            float4 kv = *(const float4*)&Kt[r * 48 + dq];
            Ks[r][dq + 0] = f2tf(kv.x); Ks[r][dq + 1] = f2tf(kv.y);
            Ks[r][dq + 2] = f2tf(kv.z); Ks[r][dq + 3] = f2tf(kv.w);
            float4 vv = *(const float4*)&Vt[r * 48 + dq];
            Vs[r][dq + 0] = f2tf(vv.x); Vs[r][dq + 1] = f2tf(vv.y);
            Vs[r][dq + 2] = f2tf(vv.z); Vs[r][dq + 3] = f2tf(vv.w);
        }
        __syncthreads();  // (B) K/V ready

        float sacc[4][4];
        #pragma unroll
        for (int nt = 0; nt < 4; nt++)
            #pragma unroll
            for (int r = 0; r < 4; r++) sacc[nt][r] = 0.f;

        #pragma unroll
        for (int ks = 0; ks < 6; ks++) {
            #pragma unroll
            for (int nt = 0; nt < 4; nt++) {
                int nn = wn * 32 + nt * 8 + group;
                uint32_t b0 = Ks[nn][ks * 8 + tid4];
                uint32_t b1 = Ks[nn][ks * 8 + tid4 + 4];
                mma8(sacc[nt][0], sacc[nt][1], sacc[nt][2], sacc[nt][3],
                     qf[ks][0], qf[ks][1], qf[ks][2], qf[ks][3], b0, b1);
            }
        }

        if (tile == blockIdx.x) {  // diagonal tile: causal mask (local coords)
            #pragma unroll
            for (int nt = 0; nt < 4; nt++) {
                int c0 = wn * 32 + nt * 8 + tid4 * 2;
                if (c0 > r0)     sacc[nt][0] = -1.0e30f;
                if (c0 + 1 > r0) sacc[nt][1] = -1.0e30f;
                if (c0 > r1)     sacc[nt][2] = -1.0e30f;
                if (c0 + 1 > r1) sacc[nt][3] = -1.0e30f;
            }
        }

        // Row-max partials (warp covers 32 cols per row)
        float mx0 = -3.0e38f, mx1 = -3.0e38f;
        #pragma unroll
        for (int nt = 0; nt < 4; nt++) {
            mx0 = fmaxf(mx0, fmaxf(sacc[nt][0], sacc[nt][1]));
            mx1 = fmaxf(mx1, fmaxf(sacc[nt][2], sacc[nt][3]));
        }
        mx0 = fmaxf(mx0, __shfl_xor_sync(0xffffffffu, mx0, 1));
        mx0 = fmaxf(mx0, __shfl_xor_sync(0xffffffffu, mx0, 2));
        mx1 = fmaxf(mx1, __shfl_xor_sync(0xffffffffu, mx1, 1));
        mx1 = fmaxf(mx1, __shfl_xor_sync(0xffffffffu, mx1, 2));
        if (tid4 == 0) { rmax_p[wn][r0] = mx0; rmax_p[wn][r1] = mx1; }
        __syncthreads();  // (C) partials ready

        float m_old0 = row_m[r0], m_old1 = row_m[r1];
        float nm0 = fmaxf(m_old0, fmaxf(rmax_p[0][r0], rmax_p[1][r0]));
        float nm1 = fmaxf(m_old1, fmaxf(rmax_p[0][r1], rmax_p[1][r1]));

        float sum0 = 0.f, sum1 = 0.f;
        #pragma unroll
        for (int nt = 0; nt < 4; nt++) {
            int c = wn * 32 + nt * 8 + tid4 * 2;
            float p0 = __expf(sacc[nt][0] - nm0);
            float p1 = __expf(sacc[nt][1] - nm0);
            float p2 = __expf(sacc[nt][2] - nm1);
            float p3 = __expf(sacc[nt][3] - nm1);
            sum0 += p0 + p1; sum1 += p2 + p3;
            Ps[r0][c] = f2tf(p0); Ps[r0][c + 1] = f2tf(p1);
            Ps[r1][c] = f2tf(p2); Ps[r1][c + 1] = f2tf(p3);
        }
        sum0 += __shfl_xor_sync(0xffffffffu, sum0, 1);
        sum0 += __shfl_xor_sync(0xffffffffu, sum0, 2);
        sum1 += __shfl_xor_sync(0xffffffffu, sum1, 1);
        sum1 += __shfl_xor_sync(0xffffffffu, sum1, 2);
        if (tid4 == 0) { rsum_p[wn][r0] = sum0; rsum_p[wn][r1] = sum1; }

        // Rescale O accumulators
        float sc0 = __expf(m_old0 - nm0);
        float sc1 = __expf(m_old1 - nm1);
        #pragma unroll
        for (int nt = 0; nt < 3; nt++) {
            oacc[nt][0] *= sc0; oacc[nt][1] *= sc0;
            oacc[nt][2] *= sc1; oacc[nt][3] *= sc1;
        }
        __syncthreads();  // (D) P + sum partials ready

        // Stats update (one owner per row; next read is after next (C))
        if (wn == 0 && tid4 == 0) {
            row_l[r0] = row_l[r0] * sc0 + rsum_p[0][r0] + rsum_p[1][r0];
            row_m[r0] = nm0;
            row_l[r1] = row_l[r1] * sc1 + rsum_p[0][r1] + rsum_p[1][r1];
            row_m[r1] = nm1;
        }

        // PV: O += P @ V
        #pragma unroll
        for (int kb = 0; kb < 8; kb++) {
            uint32_t a0 = Ps[r0][kb * 8 + tid4];
            uint32_t a1 = Ps[r1][kb * 8 + tid4];
            uint32_t a2 = Ps[r0][kb * 8 + tid4 + 4];
            uint32_t a3 = Ps[r1][kb * 8 + tid4 + 4];
            #pragma unroll
            for (int nt = 0; nt < 3; nt++) {
                int dd = wn * 24 + nt * 8 + group;
                uint32_t b0 = Vs[kb * 8 + tid4][dd];
                uint32_t b1 = Vs[kb * 8 + tid4 + 4][dd];
                mma8(oacc[nt][0], oacc[nt][1], oacc[nt][2], oacc[nt][3],
                     a0, a1, a2, a3, b0, b1);
            }
        }
    }

    __syncthreads();  // final stats visible
    float inv0 = 1.0f / row_l[r0];
    float inv1 = 1.0f / row_l[r1];
    float* Op = g_o + ((size_t)b * 2048 + m0) * 384 + h * 48;
    #pragma unroll
    for (int nt = 0; nt < 3; nt++) {
        int d = wn * 24 + nt * 8 + tid4 * 2;
        *(float2*)&Op[(size_t)r0 * 384 + d] = make_float2(oacc[nt][0] * inv0, oacc[nt][1] * inv0);
        *(float2*)&Op[(size_t)r1 * 384 + d] = make_float2(oacc[nt][2] * inv1, oacc[nt][3] * inv1);
    }
}

// ---------------------------------------------------------------------------
extern "C" void kernel_launch(void* const* d_in, const int* in_sizes, int n_in,
                              void* d_out, int out_size)
{
    const float* x  = (const float*)d_in[0];
    const float* wq = (const float*)d_in[1];
    const float* wk = (const float*)d_in[2];
    const float* wv = (const float*)d_in[3];
    const float* wo = (const float*)d_in[4];
    const float* bo = (const float*)d_in[5];
    float* out = (float*)d_out;

    rope_table_kernel<<<(T_*HALF_D + 255)/256, 256>>>();

    // Fused QKV projection + RoPE epilogue (logical N = 576)
    gemm_tc<0><<<dim3(9, MROWS/128), 256>>>(x, wq, wk, wv, nullptr, nullptr);

    // Flash attention (TF32 tensor cores)
    attn_tc<<<dim3(T_/64, B_*HQ_), 256>>>();

    // Output projection + bias
    gemm_tc<1><<<dim3(6, MROWS/128), 256>>>(nullptr, wo, nullptr, nullptr, bo, out);
}

// round 4
// speedup vs baseline: 3.3412x; 1.3104x over previous
#include <cuda_runtime.h>
#include <cuda_fp16.h>
#include <math.h>
#include <stdint.h>

#define B_  8
#define T_  2048
#define NE_ 384
#define HQ_ 8
#define HKV_ 2
#define D_  48
#define MROWS (B_*T_)
#define HALF_D 24

// Scratch (device globals; no allocations allowed)
__device__ float g_q[(size_t)B_*HQ_*T_*D_];    // [B,HQ,T,D]  (rope applied)
__device__ float g_k[(size_t)B_*HKV_*T_*D_];   // [B,HKV,T,D] (rope applied)
__device__ float g_v[(size_t)B_*HKV_*T_*D_];   // [B,HKV,T,D]
__device__ float g_o[(size_t)B_*T_*NE_];       // [B,T,NE] attention output
__device__ float g_cos[T_*HALF_D];
__device__ float g_sin[T_*HALF_D];

// ---------------------------------------------------------------------------
__device__ __forceinline__ uint32_t f2tf(float x) {
    uint32_t u;
    asm("cvt.rna.tf32.f32 %0, %1;" : "=r"(u) : "f"(x));
    return u;
}

__device__ __forceinline__ void mma8(float& d0, float& d1, float& d2, float& d3,
                                     uint32_t a0, uint32_t a1, uint32_t a2, uint32_t a3,
                                     uint32_t b0, uint32_t b1) {
    asm volatile("mma.sync.aligned.m16n8k8.row.col.f32.tf32.tf32.f32 "
                 "{%0,%1,%2,%3},{%4,%5,%6,%7},{%8,%9},{%0,%1,%2,%3};"
                 : "+f"(d0), "+f"(d1), "+f"(d2), "+f"(d3)
                 : "r"(a0), "r"(a1), "r"(a2), "r"(a3), "r"(b0), "r"(b1));
}

__device__ __forceinline__ void mma16h(float& d0, float& d1, float& d2, float& d3,
                                       uint32_t a0, uint32_t a1, uint32_t a2, uint32_t a3,
                                       uint32_t b0, uint32_t b1) {
    asm volatile("mma.sync.aligned.m16n8k16.row.col.f32.f16.f16.f32 "
                 "{%0,%1,%2,%3},{%4,%5,%6,%7},{%8,%9},{%0,%1,%2,%3};"
                 : "+f"(d0), "+f"(d1), "+f"(d2), "+f"(d3)
                 : "r"(a0), "r"(a1), "r"(a2), "r"(a3), "r"(b0), "r"(b1));
}

__device__ __forceinline__ void cpa16(uint32_t dst, const void* src) {
    asm volatile("cp.async.cg.shared.global [%0], [%1], 16;" :: "r"(dst), "l"(src) : "memory");
}
__device__ __forceinline__ uint32_t h2bits(__half2 h) {
    return *reinterpret_cast<uint32_t*>(&h);
}

// ---------------------------------------------------------------------------
// RoPE table: fp32 angle (matches jax), accurate double trig.
// ---------------------------------------------------------------------------
__global__ void rope_table_kernel() {
    int idx = blockIdx.x * blockDim.x + threadIdx.x;
    if (idx >= T_ * HALF_D) return;
    int t = idx / HALF_D, p = idx % HALF_D;
    float inv = 1.0f / powf(10000.0f, (2.0f * (float)p) / 48.0f);
    float ang = (float)t * inv;
    g_cos[idx] = (float)cos((double)ang);
    g_sin[idx] = (float)sin((double)ang);
}

// ---------------------------------------------------------------------------
// TF32 tensor-core GEMM with cp.async 3-stage pipeline.
// MODE 0: fused QKV (N=576 logical) + RoPE epilogue scatter.
// MODE 1: out-proj (N=384) + bias.
// Block tile 128x64, 8 warps 4(M)x2(N), BK=16, 24 K-slices.
// ---------------------------------------------------------------------------
template<int MODE>
__global__ __launch_bounds__(256) void gemm_tc(
    const float* __restrict__ A_in, const float* __restrict__ wq,
    const float* __restrict__ wk, const float* __restrict__ wv,
    const float* __restrict__ bias, float* __restrict__ Cout)
{
    __shared__ float As[3][128][20];   // raw fp32; pad 20 -> conflict-free frags
    __shared__ float Bs[3][16][72];    // raw fp32; pad 72 -> conflict-free frags

    const float* A = (MODE == 0) ? A_in : (const float*)g_o;
    int tid  = threadIdx.x;
    int lane = tid & 31, wid = tid >> 5;
    int wm = wid & 3, wn = wid >> 2;
    int group = lane >> 2, tid4 = lane & 3;
    int bm = blockIdx.y * 128;
    int bn = blockIdx.x * 64;

    uint32_t as_base = (uint32_t)__cvta_generic_to_shared(&As[0][0][0]);
    uint32_t bs_base = (uint32_t)__cvta_generic_to_shared(&Bs[0][0][0]);

    // async-load one 16-wide K slice into stage s
    auto loadTile = [&](int s, int kt) {
        #pragma unroll
        for (int i = tid; i < 512; i += 256) {
            int r = i >> 2, c4 = (i & 3) * 4;
            cpa16(as_base + (uint32_t)(((s*128 + r)*20 + c4) * 4),
                  &A[(size_t)(bm + r) * NE_ + kt*16 + c4]);
        }
        {
            int r = tid >> 4, c4 = (tid & 15) * 4;
            int col = bn + c4;
            const float* src;
            if (MODE == 1)       src = &wq[(size_t)(kt*16 + r) * 384 + col];
            else if (col < 384)  src = &wq[(size_t)(kt*16 + r) * 384 + col];
            else if (col < 480)  src = &wk[(size_t)(kt*16 + r) * 96 + col - 384];
            else                 src = &wv[(size_t)(kt*16 + r) * 96 + col - 480];
            cpa16(bs_base + (uint32_t)(((s*16 + r)*72 + c4) * 4), src);
        }
        asm volatile("cp.async.commit_group;" ::: "memory");
    };

    float acc[2][4][4];
    #pragma unroll
    for (int mt = 0; mt < 2; mt++)
        #pragma unroll
        for (int nt = 0; nt < 4; nt++)
            #pragma unroll
            for (int r = 0; r < 4; r++) acc[mt][nt][r] = 0.f;

    loadTile(0, 0);
    loadTile(1, 1);

    for (int kt = 0; kt < 24; kt++) {
        int s = kt % 3;
        if (kt < 23) asm volatile("cp.async.wait_group 1;" ::: "memory");
        else         asm volatile("cp.async.wait_group 0;" ::: "memory");
        __syncthreads();
        if (kt + 2 < 24) loadTile((kt + 2) % 3, kt + 2);

        #pragma unroll
        for (int ks = 0; ks < 2; ks++) {
            uint32_t af[2][4], bf[4][2];
            #pragma unroll
            for (int mt = 0; mt < 2; mt++) {
                int row = wm * 32 + mt * 16 + group;
                af[mt][0] = f2tf(As[s][row][ks*8 + tid4]);
                af[mt][1] = f2tf(As[s][row + 8][ks*8 + tid4]);
                af[mt][2] = f2tf(As[s][row][ks*8 + tid4 + 4]);
                af[mt][3] = f2tf(As[s][row + 8][ks*8 + tid4 + 4]);
            }
            #pragma unroll
            for (int nt = 0; nt < 4; nt++) {
                int nn = wn * 32 + nt * 8 + group;
                bf[nt][0] = f2tf(Bs[s][ks*8 + tid4][nn]);
                bf[nt][1] = f2tf(Bs[s][ks*8 + tid4 + 4][nn]);
            }
            #pragma unroll
            for (int mt = 0; mt < 2; mt++)
                #pragma unroll
                for (int nt = 0; nt < 4; nt++)
                    mma8(acc[mt][nt][0], acc[mt][nt][1], acc[mt][nt][2], acc[mt][nt][3],
                         af[mt][0], af[mt][1], af[mt][2], af[mt][3],
                         bf[nt][0], bf[nt][1]);
        }
        __syncthreads();
    }

    // Epilogue: accumulator holds adjacent col pairs (RoPE pairs).
    #pragma unroll
    for (int mt = 0; mt < 2; mt++) {
        #pragma unroll
        for (int nt = 0; nt < 4; nt++) {
            int col = bn + wn * 32 + nt * 8 + tid4 * 2;
            #pragma unroll
            for (int half = 0; half < 2; half++) {
                int row = bm + wm * 32 + mt * 16 + group + half * 8;
                float e = acc[mt][nt][half * 2 + 0];
                float o = acc[mt][nt][half * 2 + 1];
                if (MODE == 1) {
                    Cout[(size_t)row * 384 + col]     = e + bias[col];
                    Cout[(size_t)row * 384 + col + 1] = o + bias[col + 1];
                } else {
                    int b = row >> 11, t = row & 2047;
                    if (col < 480) {   // q or k: apply RoPE
                        int lc = (col < 384) ? col : col - 384;
                        int h = lc / 48, d = lc % 48, p = d >> 1;
                        float cc = g_cos[t * 24 + p], ss = g_sin[t * 24 + p];
                        float re = e * cc - o * ss;
                        float ro = e * ss + o * cc;
                        if (col < 384) {
                            size_t base = (((size_t)b * 8 + h) * 2048 + t) * 48 + d;
                            g_q[base] = re; g_q[base + 1] = ro;
                        } else {
                            size_t base = (((size_t)b * 2 + h) * 2048 + t) * 48 + d;
                            g_k[base] = re; g_k[base + 1] = ro;
                        }
                    } else {           // v: direct
                        int lc = col - 480;
                        int h = lc / 48, d = lc % 48;
                        size_t base = (((size_t)b * 2 + h) * 2048 + t) * 48 + d;
                        g_v[base] = e; g_v[base + 1] = o;
                    }
                }
            }
        }
    }
}

// ---------------------------------------------------------------------------
// Flash attention: 4 warps, each warp owns 16 Q rows x ALL 64 KV cols.
// QK via tf32 m16n8k8 (Q frags in regs, K in smem tf32).
// Softmax fully warp-local (stats in registers, shfl over tid4).
// P goes straight from accumulators into fp16 m16n8k16 A-frags (no smem).
// V in smem transposed fp16 [d][k] (pad 72 -> conflict-free half2 b-frags).
// Grid: (T/64, B*HQ), 128 threads. q-tiles processed in reverse for balance.
// ---------------------------------------------------------------------------
__global__ __launch_bounds__(128) void attn_tc() {
    __shared__ uint32_t Ks[64][52];    // tf32 bits; also Q staging
    __shared__ __half   Vsm[48][72];   // V transposed [d][k]

    int tid = threadIdx.x, lane = tid & 31, wm = tid >> 5;
    int group = lane >> 2, tid4 = lane & 3;
    int bh = blockIdx.y, b = bh >> 3, h = bh & 7, hk = h >> 2;
    int qt = gridDim.x - 1 - blockIdx.x;     // heavy tiles first
    int m0 = qt * 64;

    const float* Qp = g_q + (((size_t)b * 8 + h) * 2048 + m0) * 48;
    const float* Kp = g_k + ((size_t)b * 2 + hk) * 2048 * 48;
    const float* Vp = g_v + ((size_t)b * 2 + hk) * 2048 * 48;

    // Stage Q (scaled, tf32) through Ks, pull fragments to registers.
    const float scale = 0.14433756729740643f;  // 1/sqrt(48)
    for (int i = tid; i < 768; i += 128) {
        int r = i / 12, dq = (i % 12) * 4;
        float4 v = *(const float4*)&Qp[r * 48 + dq];
        Ks[r][dq + 0] = f2tf(v.x * scale);
        Ks[r][dq + 1] = f2tf(v.y * scale);
        Ks[r][dq + 2] = f2tf(v.z * scale);
        Ks[r][dq + 3] = f2tf(v.w * scale);
    }
    __syncthreads();

    int r0 = wm * 16 + group;                // rows r0, r0+8
    uint32_t qf[6][4];
    #pragma unroll
    for (int ks = 0; ks < 6; ks++) {
        qf[ks][0] = Ks[r0][ks * 8 + tid4];
        qf[ks][1] = Ks[r0 + 8][ks * 8 + tid4];
        qf[ks][2] = Ks[r0][ks * 8 + tid4 + 4];
        qf[ks][3] = Ks[r0 + 8][ks * 8 + tid4 + 4];
    }

    float oacc[6][4];
    #pragma unroll
    for (int nt = 0; nt < 6; nt++)
        #pragma unroll
        for (int r = 0; r < 4; r++) oacc[nt][r] = 0.f;
    float m0r = -3.0e38f, m1r = -3.0e38f, l0r = 0.f, l1r = 0.f;

    int ntiles = qt + 1;
    for (int tile = 0; tile < ntiles; tile++) {
        __syncthreads();  // (A) qf reads / prev PV done
        const float* Kt = Kp + (size_t)tile * 64 * 48;
        const float* Vg = Vp + (size_t)tile * 64 * 48;
        for (int i = tid; i < 768; i += 128) {
            int r = i / 12, dq = (i % 12) * 4;
            float4 kv = *(const float4*)&Kt[r * 48 + dq];
            Ks[r][dq + 0] = f2tf(kv.x); Ks[r][dq + 1] = f2tf(kv.y);
            Ks[r][dq + 2] = f2tf(kv.z); Ks[r][dq + 3] = f2tf(kv.w);
            float4 vv = *(const float4*)&Vg[r * 48 + dq];
            Vsm[dq + 0][r] = __float2half(vv.x);
            Vsm[dq + 1][r] = __float2half(vv.y);
            Vsm[dq + 2][r] = __float2half(vv.z);
            Vsm[dq + 3][r] = __float2half(vv.w);
        }
        __syncthreads();  // (B) K/V ready

        // S = Q @ K^T : warp covers 16 rows x 64 cols
        float sacc[8][4];
        #pragma unroll
        for (int nt = 0; nt < 8; nt++)
            #pragma unroll
            for (int r = 0; r < 4; r++) sacc[nt][r] = 0.f;
        #pragma unroll
        for (int ks = 0; ks < 6; ks++) {
            #pragma unroll
            for (int nt = 0; nt < 8; nt++) {
                int nn = nt * 8 + group;
                uint32_t b0 = Ks[nn][ks * 8 + tid4];
                uint32_t b1 = Ks[nn][ks * 8 + tid4 + 4];
                mma8(sacc[nt][0], sacc[nt][1], sacc[nt][2], sacc[nt][3],
                     qf[ks][0], qf[ks][1], qf[ks][2], qf[ks][3], b0, b1);
            }
        }

        if (tile == qt) {  // diagonal tile: causal mask (local coords)
            #pragma unroll
            for (int nt = 0; nt < 8; nt++) {
                int c0 = nt * 8 + tid4 * 2;
                if (c0 > r0)         sacc[nt][0] = -1.0e30f;
                if (c0 + 1 > r0)     sacc[nt][1] = -1.0e30f;
                if (c0 > r0 + 8)     sacc[nt][2] = -1.0e30f;
                if (c0 + 1 > r0 + 8) sacc[nt][3] = -1.0e30f;
            }
        }

        // Warp-local online softmax (stats live in registers)
        float mx0 = -3.0e38f, mx1 = -3.0e38f;
        #pragma unroll
        for (int nt = 0; nt < 8; nt++) {
            mx0 = fmaxf(mx0, fmaxf(sacc[nt][0], sacc[nt][1]));
            mx1 = fmaxf(mx1, fmaxf(sacc[nt][2], sacc[nt][3]));
        }
        mx0 = fmaxf(mx0, __shfl_xor_sync(0xffffffffu, mx0, 1));
        mx0 = fmaxf(mx0, __shfl_xor_sync(0xffffffffu, mx0, 2));
        mx1 = fmaxf(mx1, __shfl_xor_sync(0xffffffffu, mx1, 1));
        mx1 = fmaxf(mx1, __shfl_xor_sync(0xffffffffu, mx1, 2));

        float nm0 = fmaxf(m0r, mx0), nm1 = fmaxf(m1r, mx1);
        float sc0 = __expf(m0r - nm0), sc1 = __expf(m1r - nm1);

        uint32_t ph[8][2];
        float s0 = 0.f, s1 = 0.f;
        #pragma unroll
        for (int nt = 0; nt < 8; nt++) {
            float p0 = __expf(sacc[nt][0] - nm0);
            float p1 = __expf(sacc[nt][1] - nm0);
            float p2 = __expf(sacc[nt][2] - nm1);
            float p3 = __expf(sacc[nt][3] - nm1);
            s0 += p0 + p1; s1 += p2 + p3;
            ph[nt][0] = h2bits(__floats2half2_rn(p0, p1));
            ph[nt][1] = h2bits(__floats2half2_rn(p2, p3));
        }
        s0 += __shfl_xor_sync(0xffffffffu, s0, 1);
        s0 += __shfl_xor_sync(0xffffffffu, s0, 2);
        s1 += __shfl_xor_sync(0xffffffffu, s1, 1);
        s1 += __shfl_xor_sync(0xffffffffu, s1, 2);
        l0r = l0r * sc0 + s0;  m0r = nm0;
        l1r = l1r * sc1 + s1;  m1r = nm1;

        #pragma unroll
        for (int nt = 0; nt < 6; nt++) {
            oacc[nt][0] *= sc0; oacc[nt][1] *= sc0;
            oacc[nt][2] *= sc1; oacc[nt][3] *= sc1;
        }

        // O += P @ V  (P from registers, fp16 m16n8k16)
        #pragma unroll
        for (int kb = 0; kb < 4; kb++) {
            uint32_t a0 = ph[2*kb][0], a1 = ph[2*kb][1];
            uint32_t a2 = ph[2*kb + 1][0], a3 = ph[2*kb + 1][1];
            #pragma unroll
            for (int nt = 0; nt < 6; nt++) {
                int d = nt * 8 + group;
                uint32_t b0 = *(const uint32_t*)&Vsm[d][kb * 16 + 2 * tid4];
                uint32_t b1 = *(const uint32_t*)&Vsm[d][kb * 16 + 8 + 2 * tid4];
                mma16h(oacc[nt][0], oacc[nt][1], oacc[nt][2], oacc[nt][3],
                       a0, a1, a2, a3, b0, b1);
            }
        }
    }

    float inv0 = 1.0f / l0r, inv1 = 1.0f / l1r;
    float* Op = g_o + ((size_t)b * 2048 + m0) * 384 + h * 48;
    #pragma unroll
    for (int nt = 0; nt < 6; nt++) {
        int d = nt * 8 + 2 * tid4;
        *(float2*)&Op[(size_t)r0 * 384 + d] =
            make_float2(oacc[nt][0] * inv0, oacc[nt][1] * inv0);
        *(float2*)&Op[(size_t)(r0 + 8) * 384 + d] =
            make_float2(oacc[nt][2] * inv1, oacc[nt][3] * inv1);
    }
}

// ---------------------------------------------------------------------------
extern "C" void kernel_launch(void* const* d_in, const int* in_sizes, int n_in,
                              void* d_out, int out_size)
{
    const float* x  = (const float*)d_in[0];
    const float* wq = (const float*)d_in[1];
    const float* wk = (const float*)d_in[2];
    const float* wv = (const float*)d_in[3];
    const float* wo = (const float*)d_in[4];
    const float* bo = (const float*)d_in[5];
    float* out = (float*)d_out;

    rope_table_kernel<<<(T_*HALF_D + 255)/256, 256>>>();

    // Fused QKV projection + RoPE epilogue (logical N = 576)
    gemm_tc<0><<<dim3(9, MROWS/128), 256>>>(x, wq, wk, wv, nullptr, nullptr);

    // Flash attention
    attn_tc<<<dim3(T_/64, B_*HQ_), 128>>>();

    // Output projection + bias
    gemm_tc<1><<<dim3(6, MROWS/128), 256>>>(nullptr, wo, nullptr, nullptr, bo, out);
}

// round 5
// speedup vs baseline: 3.6512x; 1.0928x over previous
#include <cuda_runtime.h>
#include <cuda_fp16.h>
#include <math.h>
#include <stdint.h>

#define B_  8
#define T_  2048
#define NE_ 384
#define HQ_ 8
#define HKV_ 2
#define D_  48
#define MROWS (B_*T_)
#define HALF_D 24

// Scratch (device globals; no allocations allowed)
__device__ __half g_q[(size_t)B_*HQ_*T_*D_];   // [B,HQ,T,D] rope'd, pre-scaled
__device__ __half g_k[(size_t)B_*HKV_*T_*D_];  // [B,HKV,T,D] rope'd
__device__ __half g_v[(size_t)B_*HKV_*D_*T_];  // [B,HKV,D,T] TRANSPOSED
__device__ float  g_o[(size_t)B_*T_*NE_];      // [B,T,NE] attention output
__device__ float  g_cos[T_*HALF_D];
__device__ float  g_sin[T_*HALF_D];

// ---------------------------------------------------------------------------
__device__ __forceinline__ uint32_t f2tf(float x) {
    uint32_t u;
    asm("cvt.rna.tf32.f32 %0, %1;" : "=r"(u) : "f"(x));
    return u;
}
__device__ __forceinline__ void mma8(float& d0, float& d1, float& d2, float& d3,
                                     uint32_t a0, uint32_t a1, uint32_t a2, uint32_t a3,
                                     uint32_t b0, uint32_t b1) {
    asm volatile("mma.sync.aligned.m16n8k8.row.col.f32.tf32.tf32.f32 "
                 "{%0,%1,%2,%3},{%4,%5,%6,%7},{%8,%9},{%0,%1,%2,%3};"
                 : "+f"(d0), "+f"(d1), "+f"(d2), "+f"(d3)
                 : "r"(a0), "r"(a1), "r"(a2), "r"(a3), "r"(b0), "r"(b1));
}
__device__ __forceinline__ void mma16h(float& d0, float& d1, float& d2, float& d3,
                                       uint32_t a0, uint32_t a1, uint32_t a2, uint32_t a3,
                                       uint32_t b0, uint32_t b1) {
    asm volatile("mma.sync.aligned.m16n8k16.row.col.f32.f16.f16.f32 "
                 "{%0,%1,%2,%3},{%4,%5,%6,%7},{%8,%9},{%0,%1,%2,%3};"
                 : "+f"(d0), "+f"(d1), "+f"(d2), "+f"(d3)
                 : "r"(a0), "r"(a1), "r"(a2), "r"(a3), "r"(b0), "r"(b1));
}
__device__ __forceinline__ void cpa16(uint32_t dst, const void* src) {
    asm volatile("cp.async.cg.shared.global [%0], [%1], 16;" :: "r"(dst), "l"(src) : "memory");
}
__device__ __forceinline__ uint32_t h2bits(__half2 h) {
    return *reinterpret_cast<uint32_t*>(&h);
}

// ---------------------------------------------------------------------------
__global__ void rope_table_kernel() {
    int idx = blockIdx.x * blockDim.x + threadIdx.x;
    if (idx >= T_ * HALF_D) return;
    int t = idx / HALF_D, p = idx % HALF_D;
    float inv = 1.0f / powf(10000.0f, (2.0f * (float)p) / 48.0f);
    float ang = (float)t * inv;
    g_cos[idx] = (float)cos((double)ang);
    g_sin[idx] = (float)sin((double)ang);
}

// ---------------------------------------------------------------------------
// TF32 tensor-core GEMM with cp.async 3-stage pipeline.
// MODE 0: fused QKV (N=576 logical): epilogue ropes q/k, scales q, stores
//         fp16 head-major; v stored fp16 TRANSPOSED [d][t].
// MODE 1: out-proj (N=384) + bias -> fp32 out.
// ---------------------------------------------------------------------------
template<int MODE>
__global__ __launch_bounds__(256) void gemm_tc(
    const float* __restrict__ A_in, const float* __restrict__ wq,
    const float* __restrict__ wk, const float* __restrict__ wv,
    const float* __restrict__ bias, float* __restrict__ Cout)
{
    __shared__ float As[3][128][20];
    __shared__ float Bs[3][16][72];

    const float* A = (MODE == 0) ? A_in : (const float*)g_o;
    int tid  = threadIdx.x;
    int lane = tid & 31, wid = tid >> 5;
    int wm = wid & 3, wn = wid >> 2;
    int group = lane >> 2, tid4 = lane & 3;
    int bm = blockIdx.y * 128;
    int bn = blockIdx.x * 64;

    uint32_t as_base = (uint32_t)__cvta_generic_to_shared(&As[0][0][0]);
    uint32_t bs_base = (uint32_t)__cvta_generic_to_shared(&Bs[0][0][0]);

    auto loadTile = [&](int s, int kt) {
        #pragma unroll
        for (int i = tid; i < 512; i += 256) {
            int r = i >> 2, c4 = (i & 3) * 4;
            cpa16(as_base + (uint32_t)(((s*128 + r)*20 + c4) * 4),
                  &A[(size_t)(bm + r) * NE_ + kt*16 + c4]);
        }
        {
            int r = tid >> 4, c4 = (tid & 15) * 4;
            int col = bn + c4;
            const float* src;
            if (MODE == 1)       src = &wq[(size_t)(kt*16 + r) * 384 + col];
            else if (col < 384)  src = &wq[(size_t)(kt*16 + r) * 384 + col];
            else if (col < 480)  src = &wk[(size_t)(kt*16 + r) * 96 + col - 384];
            else                 src = &wv[(size_t)(kt*16 + r) * 96 + col - 480];
            cpa16(bs_base + (uint32_t)(((s*16 + r)*72 + c4) * 4), src);
        }
        asm volatile("cp.async.commit_group;" ::: "memory");
    };

    float acc[2][4][4];
    #pragma unroll
    for (int mt = 0; mt < 2; mt++)
        #pragma unroll
        for (int nt = 0; nt < 4; nt++)
            #pragma unroll
            for (int r = 0; r < 4; r++) acc[mt][nt][r] = 0.f;

    loadTile(0, 0);
    loadTile(1, 1);

    for (int kt = 0; kt < 24; kt++) {
        int s = kt % 3;
        if (kt < 23) asm volatile("cp.async.wait_group 1;" ::: "memory");
        else         asm volatile("cp.async.wait_group 0;" ::: "memory");
        __syncthreads();
        if (kt + 2 < 24) loadTile((kt + 2) % 3, kt + 2);

        #pragma unroll
        for (int ks = 0; ks < 2; ks++) {
            uint32_t af[2][4], bf[4][2];
            #pragma unroll
            for (int mt = 0; mt < 2; mt++) {
                int row = wm * 32 + mt * 16 + group;
                af[mt][0] = f2tf(As[s][row][ks*8 + tid4]);
                af[mt][1] = f2tf(As[s][row + 8][ks*8 + tid4]);
                af[mt][2] = f2tf(As[s][row][ks*8 + tid4 + 4]);
                af[mt][3] = f2tf(As[s][row + 8][ks*8 + tid4 + 4]);
            }
            #pragma unroll
            for (int nt = 0; nt < 4; nt++) {
                int nn = wn * 32 + nt * 8 + group;
                bf[nt][0] = f2tf(Bs[s][ks*8 + tid4][nn]);
                bf[nt][1] = f2tf(Bs[s][ks*8 + tid4 + 4][nn]);
            }
            #pragma unroll
            for (int mt = 0; mt < 2; mt++)
                #pragma unroll
                for (int nt = 0; nt < 4; nt++)
                    mma8(acc[mt][nt][0], acc[mt][nt][1], acc[mt][nt][2], acc[mt][nt][3],
                         af[mt][0], af[mt][1], af[mt][2], af[mt][3],
                         bf[nt][0], bf[nt][1]);
        }
        __syncthreads();
    }

    const float scale = 0.14433756729740643f; // 1/sqrt(48)
    #pragma unroll
    for (int mt = 0; mt < 2; mt++) {
        #pragma unroll
        for (int nt = 0; nt < 4; nt++) {
            int col = bn + wn * 32 + nt * 8 + tid4 * 2;
            #pragma unroll
            for (int half = 0; half < 2; half++) {
                int row = bm + wm * 32 + mt * 16 + group + half * 8;
                float e = acc[mt][nt][half * 2 + 0];
                float o = acc[mt][nt][half * 2 + 1];
                if (MODE == 1) {
                    Cout[(size_t)row * 384 + col]     = e + bias[col];
                    Cout[(size_t)row * 384 + col + 1] = o + bias[col + 1];
                } else {
                    int b = row >> 11, t = row & 2047;
                    if (col < 480) {   // q or k: RoPE
                        int lc = (col < 384) ? col : col - 384;
                        int h = lc / 48, d = lc % 48, p = d >> 1;
                        float cc = g_cos[t * 24 + p], ss = g_sin[t * 24 + p];
                        float re = e * cc - o * ss;
                        float ro = e * ss + o * cc;
                        if (col < 384) {
                            size_t base = (((size_t)b * 8 + h) * 2048 + t) * 48 + d;
                            *(__half2*)&g_q[base] = __floats2half2_rn(re * scale, ro * scale);
                        } else {
                            size_t base = (((size_t)b * 2 + h) * 2048 + t) * 48 + d;
                            *(__half2*)&g_k[base] = __floats2half2_rn(re, ro);
                        }
                    } else {           // v: transposed [d][t]
                        int lc = col - 480;
                        int h = lc / 48, d = lc % 48;
                        size_t base = ((size_t)b * 2 + h) * 48 * 2048 + (size_t)d * 2048 + t;
                        g_v[base]        = __float2half(e);
                        g_v[base + 2048] = __float2half(o);
                    }
                }
            }
        }
    }
}

// ---------------------------------------------------------------------------
// Flash attention, all-fp16 MMA, cp.async double-buffered KV.
// 4 warps, each owns 16 Q rows x all 64 KV cols; softmax warp-local.
// Grid (T/64, B*HQ), 128 threads. One __syncthreads per KV tile.
// ---------------------------------------------------------------------------
__global__ __launch_bounds__(128) void attn_tc() {
    __shared__ __align__(16) __half Ksm[2][64][56];   // [kvrow][d], pad 56
    __shared__ __align__(16) __half Vsm[2][48][72];   // [d][kvrow], pad 72

    int tid = threadIdx.x, lane = tid & 31, wm = tid >> 5;
    int group = lane >> 2, tid4 = lane & 3;
    int bh = blockIdx.y, b = bh >> 3, h = bh & 7, hk = h >> 2;
    int qt = gridDim.x - 1 - blockIdx.x;     // heavy tiles first
    int m0 = qt * 64;

    const __half* Qp = g_q + (((size_t)b * 8 + h) * 2048 + m0) * 48;
    const __half* Kp = g_k + ((size_t)b * 2 + hk) * 2048 * 48;
    const __half* Vp = g_v + ((size_t)b * 2 + hk) * 48 * 2048;  // [d][t]

    uint32_t ks_base = (uint32_t)__cvta_generic_to_shared(&Ksm[0][0][0]);
    uint32_t vs_base = (uint32_t)__cvta_generic_to_shared(&Vsm[0][0][0]);

    int r0 = wm * 16 + group;   // rows r0, r0+8

    // Q fragments straight from global (pre-scaled fp16)
    uint32_t qf[3][4];
    #pragma unroll
    for (int ks = 0; ks < 3; ks++) {
        qf[ks][0] = *(const uint32_t*)&Qp[(size_t)r0 * 48 + ks*16 + 2*tid4];
        qf[ks][1] = *(const uint32_t*)&Qp[(size_t)(r0 + 8) * 48 + ks*16 + 2*tid4];
        qf[ks][2] = *(const uint32_t*)&Qp[(size_t)r0 * 48 + ks*16 + 8 + 2*tid4];
        qf[ks][3] = *(const uint32_t*)&Qp[(size_t)(r0 + 8) * 48 + ks*16 + 8 + 2*tid4];
    }

    auto loadKV = [&](int s, int tile) {
        const __half* Kt = Kp + (size_t)tile * 64 * 48;
        const __half* Vt = Vp + tile * 64;
        #pragma unroll
        for (int i = tid; i < 384; i += 128) {
            int r = i / 6, seg = i % 6;
            cpa16(ks_base + (uint32_t)((((s*64) + r)*56 + seg*8) * 2),
                  Kt + (size_t)r * 48 + seg * 8);
        }
        #pragma unroll
        for (int i = tid; i < 384; i += 128) {
            int d = i / 8, seg = i % 8;
            cpa16(vs_base + (uint32_t)((((s*48) + d)*72 + seg*8) * 2),
                  Vt + (size_t)d * 2048 + seg * 8);
        }
        asm volatile("cp.async.commit_group;" ::: "memory");
    };

    float oacc[6][4];
    #pragma unroll
    for (int nt = 0; nt < 6; nt++)
        #pragma unroll
        for (int r = 0; r < 4; r++) oacc[nt][r] = 0.f;
    float m0r = -3.0e38f, m1r = -3.0e38f, l0r = 0.f, l1r = 0.f;

    loadKV(0, 0);

    for (int tile = 0; tile <= qt; tile++) {
        int s = tile & 1;
        asm volatile("cp.async.wait_group 0;" ::: "memory");
        __syncthreads();   // KV(s) visible; everyone done reading buffer s^1
        if (tile + 1 <= qt) loadKV(s ^ 1, tile + 1);

        // S = Q @ K^T (fp16 m16n8k16): 16 rows x 64 cols per warp
        float sacc[8][4];
        #pragma unroll
        for (int nt = 0; nt < 8; nt++)
            #pragma unroll
            for (int r = 0; r < 4; r++) sacc[nt][r] = 0.f;
        #pragma unroll
        for (int ks = 0; ks < 3; ks++) {
            #pragma unroll
            for (int nt = 0; nt < 8; nt++) {
                int nn = nt * 8 + group;
                uint32_t b0 = *(const uint32_t*)&Ksm[s][nn][ks*16 + 2*tid4];
                uint32_t b1 = *(const uint32_t*)&Ksm[s][nn][ks*16 + 8 + 2*tid4];
                mma16h(sacc[nt][0], sacc[nt][1], sacc[nt][2], sacc[nt][3],
                       qf[ks][0], qf[ks][1], qf[ks][2], qf[ks][3], b0, b1);
            }
        }

        if (tile == qt) {  // diagonal: causal mask (local coords)
            #pragma unroll
            for (int nt = 0; nt < 8; nt++) {
                int c0 = nt * 8 + tid4 * 2;
                if (c0 > r0)         sacc[nt][0] = -1.0e30f;
                if (c0 + 1 > r0)     sacc[nt][1] = -1.0e30f;
                if (c0 > r0 + 8)     sacc[nt][2] = -1.0e30f;
                if (c0 + 1 > r0 + 8) sacc[nt][3] = -1.0e30f;
            }
        }

        // Warp-local online softmax
        float mx0 = -3.0e38f, mx1 = -3.0e38f;
        #pragma unroll
        for (int nt = 0; nt < 8; nt++) {
            mx0 = fmaxf(mx0, fmaxf(sacc[nt][0], sacc[nt][1]));
            mx1 = fmaxf(mx1, fmaxf(sacc[nt][2], sacc[nt][3]));
        }
        mx0 = fmaxf(mx0, __shfl_xor_sync(0xffffffffu, mx0, 1));
        mx0 = fmaxf(mx0, __shfl_xor_sync(0xffffffffu, mx0, 2));
        mx1 = fmaxf(mx1, __shfl_xor_sync(0xffffffffu, mx1, 1));
        mx1 = fmaxf(mx1, __shfl_xor_sync(0xffffffffu, mx1, 2));

        float nm0 = fmaxf(m0r, mx0), nm1 = fmaxf(m1r, mx1);
        float sc0 = __expf(m0r - nm0), sc1 = __expf(m1r - nm1);

        uint32_t ph[8][2];
        float s0 = 0.f, s1 = 0.f;
        #pragma unroll
        for (int nt = 0; nt < 8; nt++) {
            float p0 = __expf(sacc[nt][0] - nm0);
            float p1 = __expf(sacc[nt][1] - nm0);
            float p2 = __expf(sacc[nt][2] - nm1);
            float p3 = __expf(sacc[nt][3] - nm1);
            s0 += p0 + p1; s1 += p2 + p3;
            ph[nt][0] = h2bits(__floats2half2_rn(p0, p1));
            ph[nt][1] = h2bits(__floats2half2_rn(p2, p3));
        }
        s0 += __shfl_xor_sync(0xffffffffu, s0, 1);
        s0 += __shfl_xor_sync(0xffffffffu, s0, 2);
        s1 += __shfl_xor_sync(0xffffffffu, s1, 1);
        s1 += __shfl_xor_sync(0xffffffffu, s1, 2);
        l0r = l0r * sc0 + s0;  m0r = nm0;
        l1r = l1r * sc1 + s1;  m1r = nm1;

        #pragma unroll
        for (int nt = 0; nt < 6; nt++) {
            oacc[nt][0] *= sc0; oacc[nt][1] *= sc0;
            oacc[nt][2] *= sc1; oacc[nt][3] *= sc1;
        }

        // O += P @ V (P from registers)
        #pragma unroll
        for (int kb = 0; kb < 4; kb++) {
            uint32_t a0 = ph[2*kb][0], a1 = ph[2*kb][1];
            uint32_t a2 = ph[2*kb + 1][0], a3 = ph[2*kb + 1][1];
            #pragma unroll
            for (int nt = 0; nt < 6; nt++) {
                int d = nt * 8 + group;
                uint32_t b0 = *(const uint32_t*)&Vsm[s][d][kb * 16 + 2 * tid4];
                uint32_t b1 = *(const uint32_t*)&Vsm[s][d][kb * 16 + 8 + 2 * tid4];
                mma16h(oacc[nt][0], oacc[nt][1], oacc[nt][2], oacc[nt][3],
                       a0, a1, a2, a3, b0, b1);
            }
        }
    }

    float inv0 = 1.0f / l0r, inv1 = 1.0f / l1r;
    float* Op = g_o + ((size_t)b * 2048 + m0) * 384 + h * 48;
    #pragma unroll
    for (int nt = 0; nt < 6; nt++) {
        int d = nt * 8 + 2 * tid4;
        *(float2*)&Op[(size_t)r0 * 384 + d] =
            make_float2(oacc[nt][0] * inv0, oacc[nt][1] * inv0);
        *(float2*)&Op[(size_t)(r0 + 8) * 384 + d] =
            make_float2(oacc[nt][2] * inv1, oacc[nt][3] * inv1);
    }
}

// ---------------------------------------------------------------------------
extern "C" void kernel_launch(void* const* d_in, const int* in_sizes, int n_in,
                              void* d_out, int out_size)
{
    const float* x  = (const float*)d_in[0];
    const float* wq = (const float*)d_in[1];
    const float* wk = (const float*)d_in[2];
    const float* wv = (const float*)d_in[3];
    const float* wo = (const float*)d_in[4];
    const float* bo = (const float*)d_in[5];
    float* out = (float*)d_out;

    rope_table_kernel<<<(T_*HALF_D + 255)/256, 256>>>();

    // Fused QKV projection + RoPE epilogue (logical N = 576), fp16 outputs
    gemm_tc<0><<<dim3(9, MROWS/128), 256>>>(x, wq, wk, wv, nullptr, nullptr);

    // Flash attention (fp16 MMA, double-buffered cp.async KV)
    attn_tc<<<dim3(T_/64, B_*HQ_), 128>>>();

    // Output projection + bias
    gemm_tc<1><<<dim3(6, MROWS/128), 256>>>(nullptr, wo, nullptr, nullptr, bo, out);
}

// round 8
// speedup vs baseline: 6.6442x; 1.8198x over previous
#include <cuda_runtime.h>
#include <cuda_fp16.h>
#include <math.h>
#include <stdint.h>

#define B_  8
#define T_  2048
#define NE_ 384
#define HQ_ 8
#define HKV_ 2
#define D_  48
#define MROWS (B_*T_)
#define HALF_D 24

// Scratch (device globals; no allocations allowed)
__device__ __half g_xh[(size_t)MROWS*NE_];       // x in fp16
__device__ __half g_wqkvT[(size_t)576*NE_];      // [n][k] fused wq|wk|wv, transposed
__device__ __half g_woT[(size_t)NE_*NE_];        // [n][k] wo transposed
__device__ __half g_q[(size_t)B_*HQ_*T_*D_];     // [B,HQ,T,D] rope'd, pre-scaled
__device__ __half g_k[(size_t)B_*HKV_*T_*D_];    // [B,HKV,T,D] rope'd
__device__ __half g_v[(size_t)B_*HKV_*T_*D_];    // [B,HKV,T,D]
__device__ __half g_vT[(size_t)B_*HKV_*D_*T_];   // [B,HKV,D,T] transposed
__device__ __half g_oh[(size_t)B_*T_*NE_];       // [B,T,NE] attention out fp16
__device__ float  g_cos[T_*HALF_D];
__device__ float  g_sin[T_*HALF_D];

// ---------------------------------------------------------------------------
__device__ __forceinline__ void mma16h(float& d0, float& d1, float& d2, float& d3,
                                       uint32_t a0, uint32_t a1, uint32_t a2, uint32_t a3,
                                       uint32_t b0, uint32_t b1) {
    asm volatile("mma.sync.aligned.m16n8k16.row.col.f32.f16.f16.f32 "
                 "{%0,%1,%2,%3},{%4,%5,%6,%7},{%8,%9},{%0,%1,%2,%3};"
                 : "+f"(d0), "+f"(d1), "+f"(d2), "+f"(d3)
                 : "r"(a0), "r"(a1), "r"(a2), "r"(a3), "r"(b0), "r"(b1));
}
__device__ __forceinline__ void cpa16(uint32_t dst, const void* src) {
    asm volatile("cp.async.cg.shared.global [%0], [%1], 16;" :: "r"(dst), "l"(src) : "memory");
}
__device__ __forceinline__ uint32_t h2bits(__half2 h) {
    return *reinterpret_cast<uint32_t*>(&h);
}

// ---------------------------------------------------------------------------
__global__ void rope_table_kernel() {
    int idx = blockIdx.x * blockDim.x + threadIdx.x;
    if (idx >= T_ * HALF_D) return;
    int t = idx / HALF_D, p = idx % HALF_D;
    float inv = 1.0f / powf(10000.0f, (2.0f * (float)p) / 48.0f);
    float ang = (float)t * inv;
    g_cos[idx] = (float)cos((double)ang);
    g_sin[idx] = (float)sin((double)ang);
}

// x fp32 -> fp16 (vectorized)
__global__ void conv_x_kernel(const float* __restrict__ x) {
    int i = blockIdx.x * blockDim.x + threadIdx.x;   // float4 index
    if (i >= MROWS * NE_ / 4) return;
    float4 v = ((const float4*)x)[i];
    __half2* dst = (__half2*)g_xh;
    dst[2*i]     = __floats2half2_rn(v.x, v.y);
    dst[2*i + 1] = __floats2half2_rn(v.z, v.w);
}

// W [384][N] fp32 -> fp16 transposed into g_wqkvT or g_woT:
// dst[(n0_out+n)*384 + k] = W[k][n].  DST: 0 -> g_wqkvT, 1 -> g_woT
template<int DST>
__global__ void wtrans_kernel(const float* __restrict__ W, int N, int n0_out) {
    __shared__ float tile[32][33];
    __half* dst = (DST == 0) ? g_wqkvT : g_woT;
    int k0 = blockIdx.y * 32, n0 = blockIdx.x * 32;
    int tx = threadIdx.x & 31, ty = threadIdx.x >> 5;   // 256 thr: ty 0..7
    #pragma unroll
    for (int j = 0; j < 4; j++) {
        int r = ty + j * 8;
        tile[r][tx] = W[(size_t)(k0 + r) * N + n0 + tx];
    }
    __syncthreads();
    #pragma unroll
    for (int j = 0; j < 4; j++) {
        int n = ty + j * 8;
        dst[(size_t)(n0_out + n0 + n) * 384 + k0 + tx] = __float2half(tile[tx][n]);
    }
}

// g_v [bh][t][d] -> g_vT [bh][d][t]
__global__ void vtrans_kernel() {
    __shared__ __half tile[64][56];
    int bh = blockIdx.y;
    int t0 = blockIdx.x * 64;
    int tid = threadIdx.x;
    const __half* src = g_v + (size_t)bh * 2048 * 48 + (size_t)t0 * 48;
    #pragma unroll
    for (int i = tid; i < 1536; i += 256) {       // 64 rows x 24 uint32
        int r = i / 24, c2 = i % 24;
        *(uint32_t*)&tile[r][c2 * 2] = ((const uint32_t*)src)[r * 24 + c2];
    }
    __syncthreads();
    __half* dst = g_vT + (size_t)bh * 48 * 2048 + t0;
    #pragma unroll
    for (int i = tid; i < 1536; i += 256) {       // 48 d-rows x 32 t-pairs
        int d = i / 32, tp = i % 32;
        __half2 hv = __halves2half2(tile[2 * tp][d], tile[2 * tp + 1][d]);
        *(__half2*)&dst[(size_t)d * 2048 + 2 * tp] = hv;
    }
}

// ---------------------------------------------------------------------------
// fp16 tensor-core GEMM, cp.async 3-stage, BK=32, block 128x64, 8 warps 4x2.
// MODE 0: g_xh @ g_wqkvT' (N=576) -> RoPE epilogue -> g_q/g_k/g_v fp16
// MODE 1: g_oh @ g_woT'  (N=384) -> +bias -> fp32 Cout
// Device symbols referenced directly (no host pointer plumbing).
// ---------------------------------------------------------------------------
template<int MODE>
__global__ __launch_bounds__(256) void gemm_h(
    const float* __restrict__ bias, float* __restrict__ Cout)
{
    __shared__ __half As[3][128][40];   // pad 40 -> conflict-free frags
    __shared__ __half Bs[3][64][40];

    const __half* A  = (MODE == 0) ? g_xh    : g_oh;
    const __half* BT = (MODE == 0) ? g_wqkvT : g_woT;

    int tid  = threadIdx.x;
    int lane = tid & 31, wid = tid >> 5;
    int wm = wid & 3, wn = wid >> 2;
    int group = lane >> 2, tid4 = lane & 3;
    int bm = blockIdx.y * 128;
    int bn = blockIdx.x * 64;

    uint32_t as_base = (uint32_t)__cvta_generic_to_shared(&As[0][0][0]);
    uint32_t bs_base = (uint32_t)__cvta_generic_to_shared(&Bs[0][0][0]);

    auto loadTile = [&](int s, int kt) {
        #pragma unroll
        for (int i = tid; i < 512; i += 256) {          // A: 128 rows x 4 segs
            int r = i >> 2, seg = i & 3;
            cpa16(as_base + (uint32_t)(s*10240 + r*80 + seg*16),
                  &A[(size_t)(bm + r) * NE_ + kt*32 + seg*8]);
        }
        {                                               // B: 64 rows x 4 segs
            int r = tid >> 2, seg = tid & 3;
            cpa16(bs_base + (uint32_t)(s*5120 + r*80 + seg*16),
                  &BT[(size_t)(bn + r) * NE_ + kt*32 + seg*8]);
        }
        asm volatile("cp.async.commit_group;" ::: "memory");
    };

    float acc[2][4][4];
    #pragma unroll
    for (int mt = 0; mt < 2; mt++)
        #pragma unroll
        for (int nt = 0; nt < 4; nt++)
            #pragma unroll
            for (int r = 0; r < 4; r++) acc[mt][nt][r] = 0.f;

    loadTile(0, 0);
    loadTile(1, 1);

    for (int kt = 0; kt < 12; kt++) {
        int s = kt % 3;
        if (kt < 11) asm volatile("cp.async.wait_group 1;" ::: "memory");
        else         asm volatile("cp.async.wait_group 0;" ::: "memory");
        __syncthreads();
        if (kt + 2 < 12) loadTile((kt + 2) % 3, kt + 2);

        #pragma unroll
        for (int ks = 0; ks < 2; ks++) {
            uint32_t af[2][4], bf[4][2];
            #pragma unroll
            for (int mt = 0; mt < 2; mt++) {
                int row = wm * 32 + mt * 16 + group;
                af[mt][0] = *(const uint32_t*)&As[s][row][ks*16 + 2*tid4];
                af[mt][1] = *(const uint32_t*)&As[s][row + 8][ks*16 + 2*tid4];
                af[mt][2] = *(const uint32_t*)&As[s][row][ks*16 + 8 + 2*tid4];
                af[mt][3] = *(const uint32_t*)&As[s][row + 8][ks*16 + 8 + 2*tid4];
            }
            #pragma unroll
            for (int nt = 0; nt < 4; nt++) {
                int nn = wn * 32 + nt * 8 + group;
                bf[nt][0] = *(const uint32_t*)&Bs[s][nn][ks*16 + 2*tid4];
                bf[nt][1] = *(const uint32_t*)&Bs[s][nn][ks*16 + 8 + 2*tid4];
            }
            #pragma unroll
            for (int mt = 0; mt < 2; mt++)
                #pragma unroll
                for (int nt = 0; nt < 4; nt++)
                    mma16h(acc[mt][nt][0], acc[mt][nt][1], acc[mt][nt][2], acc[mt][nt][3],
                           af[mt][0], af[mt][1], af[mt][2], af[mt][3],
                           bf[nt][0], bf[nt][1]);
        }
        __syncthreads();
    }

    const float scale = 0.14433756729740643f; // 1/sqrt(48)
    #pragma unroll
    for (int mt = 0; mt < 2; mt++) {
        #pragma unroll
        for (int nt = 0; nt < 4; nt++) {
            int col = bn + wn * 32 + nt * 8 + tid4 * 2;
            #pragma unroll
            for (int half = 0; half < 2; half++) {
                int row = bm + wm * 32 + mt * 16 + group + half * 8;
                float e = acc[mt][nt][half * 2 + 0];
                float o = acc[mt][nt][half * 2 + 1];
                if (MODE == 1) {
                    Cout[(size_t)row * 384 + col]     = e + bias[col];
                    Cout[(size_t)row * 384 + col + 1] = o + bias[col + 1];
                } else {
                    int b = row >> 11, t = row & 2047;
                    if (col < 480) {   // q or k: RoPE
                        int lc = (col < 384) ? col : col - 384;
                        int h = lc / 48, d = lc % 48, p = d >> 1;
                        float cc = g_cos[t * 24 + p], ss = g_sin[t * 24 + p];
                        float re = e * cc - o * ss;
                        float ro = e * ss + o * cc;
                        if (col < 384) {
                            size_t base = (((size_t)b * 8 + h) * 2048 + t) * 48 + d;
                            *(__half2*)&g_q[base] = __floats2half2_rn(re * scale, ro * scale);
                        } else {
                            size_t base = (((size_t)b * 2 + h) * 2048 + t) * 48 + d;
                            *(__half2*)&g_k[base] = __floats2half2_rn(re, ro);
                        }
                    } else {           // v: coalesced [t][d]
                        int lc = col - 480;
                        int h = lc / 48, d = lc % 48;
                        size_t base = (((size_t)b * 2 + h) * 2048 + t) * 48 + d;
                        *(__half2*)&g_v[base] = __floats2half2_rn(e, o);
                    }
                }
            }
        }
    }
}

// ---------------------------------------------------------------------------
// Flash attention, all-fp16 MMA, cp.async double-buffered KV.
// 4 warps, each owns 16 Q rows x all 64 KV cols; softmax warp-local.
// Grid (T/64, B*HQ), 128 threads. One __syncthreads per KV tile.
// ---------------------------------------------------------------------------
__global__ __launch_bounds__(128) void attn_tc() {
    __shared__ __align__(16) __half Ksm[2][64][56];   // [kvrow][d], pad 56
    __shared__ __align__(16) __half Vsm[2][48][72];   // [d][kvrow], pad 72

    int tid = threadIdx.x, lane = tid & 31, wm = tid >> 5;
    int group = lane >> 2, tid4 = lane & 3;
    int bh = blockIdx.y, b = bh >> 3, h = bh & 7, hk = h >> 2;
    int qt = gridDim.x - 1 - blockIdx.x;     // heavy tiles first
    int m0 = qt * 64;

    const __half* Qp = g_q + (((size_t)b * 8 + h) * 2048 + m0) * 48;
    const __half* Kp = g_k + ((size_t)b * 2 + hk) * 2048 * 48;
    const __half* Vp = g_vT + ((size_t)b * 2 + hk) * 48 * 2048;  // [d][t]

    uint32_t ks_base = (uint32_t)__cvta_generic_to_shared(&Ksm[0][0][0]);
    uint32_t vs_base = (uint32_t)__cvta_generic_to_shared(&Vsm[0][0][0]);

    int r0 = wm * 16 + group;   // rows r0, r0+8

    uint32_t qf[3][4];
    #pragma unroll
    for (int ks = 0; ks < 3; ks++) {
        qf[ks][0] = *(const uint32_t*)&Qp[(size_t)r0 * 48 + ks*16 + 2*tid4];
        qf[ks][1] = *(const uint32_t*)&Qp[(size_t)(r0 + 8) * 48 + ks*16 + 2*tid4];
        qf[ks][2] = *(const uint32_t*)&Qp[(size_t)r0 * 48 + ks*16 + 8 + 2*tid4];
        qf[ks][3] = *(const uint32_t*)&Qp[(size_t)(r0 + 8) * 48 + ks*16 + 8 + 2*tid4];
    }

    auto loadKV = [&](int s, int tile) {
        const __half* Kt = Kp + (size_t)tile * 64 * 48;
        const __half* Vt = Vp + tile * 64;
        #pragma unroll
        for (int i = tid; i < 384; i += 128) {
            int r = i / 6, seg = i % 6;
            cpa16(ks_base + (uint32_t)((((s*64) + r)*56 + seg*8) * 2),
                  Kt + (size_t)r * 48 + seg * 8);
        }
        #pragma unroll
        for (int i = tid; i < 384; i += 128) {
            int d = i / 8, seg = i % 8;
            cpa16(vs_base + (uint32_t)((((s*48) + d)*72 + seg*8) * 2),
                  Vt + (size_t)d * 2048 + seg * 8);
        }
        asm volatile("cp.async.commit_group;" ::: "memory");
    };

    float oacc[6][4];
    #pragma unroll
    for (int nt = 0; nt < 6; nt++)
        #pragma unroll
        for (int r = 0; r < 4; r++) oacc[nt][r] = 0.f;
    float m0r = -3.0e38f, m1r = -3.0e38f, l0r = 0.f, l1r = 0.f;

    loadKV(0, 0);

    for (int tile = 0; tile <= qt; tile++) {
        int s = tile & 1;
        asm volatile("cp.async.wait_group 0;" ::: "memory");
        __syncthreads();
        if (tile + 1 <= qt) loadKV(s ^ 1, tile + 1);

        float sacc[8][4];
        #pragma unroll
        for (int nt = 0; nt < 8; nt++)
            #pragma unroll
            for (int r = 0; r < 4; r++) sacc[nt][r] = 0.f;
        #pragma unroll
        for (int ks = 0; ks < 3; ks++) {
            #pragma unroll
            for (int nt = 0; nt < 8; nt++) {
                int nn = nt * 8 + group;
                uint32_t b0 = *(const uint32_t*)&Ksm[s][nn][ks*16 + 2*tid4];
                uint32_t b1 = *(const uint32_t*)&Ksm[s][nn][ks*16 + 8 + 2*tid4];
                mma16h(sacc[nt][0], sacc[nt][1], sacc[nt][2], sacc[nt][3],
                       qf[ks][0], qf[ks][1], qf[ks][2], qf[ks][3], b0, b1);
            }
        }

        if (tile == qt) {  // diagonal: causal mask
            #pragma unroll
            for (int nt = 0; nt < 8; nt++) {
                int c0 = nt * 8 + tid4 * 2;
                if (c0 > r0)         sacc[nt][0] = -1.0e30f;
                if (c0 + 1 > r0)     sacc[nt][1] = -1.0e30f;
                if (c0 > r0 + 8)     sacc[nt][2] = -1.0e30f;
                if (c0 + 1 > r0 + 8) sacc[nt][3] = -1.0e30f;
            }
        }

        float mx0 = -3.0e38f, mx1 = -3.0e38f;
        #pragma unroll
        for (int nt = 0; nt < 8; nt++) {
            mx0 = fmaxf(mx0, fmaxf(sacc[nt][0], sacc[nt][1]));
            mx1 = fmaxf(mx1, fmaxf(sacc[nt][2], sacc[nt][3]));
        }
        mx0 = fmaxf(mx0, __shfl_xor_sync(0xffffffffu, mx0, 1));
        mx0 = fmaxf(mx0, __shfl_xor_sync(0xffffffffu, mx0, 2));
        mx1 = fmaxf(mx1, __shfl_xor_sync(0xffffffffu, mx1, 1));
        mx1 = fmaxf(mx1, __shfl_xor_sync(0xffffffffu, mx1, 2));

        float nm0 = fmaxf(m0r, mx0), nm1 = fmaxf(m1r, mx1);
        float sc0 = __expf(m0r - nm0), sc1 = __expf(m1r - nm1);

        uint32_t ph[8][2];
        float s0 = 0.f, s1 = 0.f;
        #pragma unroll
        for (int nt = 0; nt < 8; nt++) {
            float p0 = __expf(sacc[nt][0] - nm0);
            float p1 = __expf(sacc[nt][1] - nm0);
            float p2 = __expf(sacc[nt][2] - nm1);
            float p3 = __expf(sacc[nt][3] - nm1);
            s0 += p0 + p1; s1 += p2 + p3;
            ph[nt][0] = h2bits(__floats2half2_rn(p0, p1));
            ph[nt][1] = h2bits(__floats2half2_rn(p2, p3));
        }
        s0 += __shfl_xor_sync(0xffffffffu, s0, 1);
        s0 += __shfl_xor_sync(0xffffffffu, s0, 2);
        s1 += __shfl_xor_sync(0xffffffffu, s1, 1);
        s1 += __shfl_xor_sync(0xffffffffu, s1, 2);
        l0r = l0r * sc0 + s0;  m0r = nm0;
        l1r = l1r * sc1 + s1;  m1r = nm1;

        #pragma unroll
        for (int nt = 0; nt < 6; nt++) {
            oacc[nt][0] *= sc0; oacc[nt][1] *= sc0;
            oacc[nt][2] *= sc1; oacc[nt][3] *= sc1;
        }

        #pragma unroll
        for (int kb = 0; kb < 4; kb++) {
            uint32_t a0 = ph[2*kb][0], a1 = ph[2*kb][1];
            uint32_t a2 = ph[2*kb + 1][0], a3 = ph[2*kb + 1][1];
            #pragma unroll
            for (int nt = 0; nt < 6; nt++) {
                int d = nt * 8 + group;
                uint32_t b0 = *(const uint32_t*)&Vsm[s][d][kb * 16 + 2 * tid4];
                uint32_t b1 = *(const uint32_t*)&Vsm[s][d][kb * 16 + 8 + 2 * tid4];
                mma16h(oacc[nt][0], oacc[nt][1], oacc[nt][2], oacc[nt][3],
                       a0, a1, a2, a3, b0, b1);
            }
        }
    }

    float inv0 = 1.0f / l0r, inv1 = 1.0f / l1r;
    __half* Op = g_oh + ((size_t)b * 2048 + m0) * 384 + h * 48;
    #pragma unroll
    for (int nt = 0; nt < 6; nt++) {
        int d = nt * 8 + 2 * tid4;
        *(__half2*)&Op[(size_t)r0 * 384 + d] =
            __floats2half2_rn(oacc[nt][0] * inv0, oacc[nt][1] * inv0);
        *(__half2*)&Op[(size_t)(r0 + 8) * 384 + d] =
            __floats2half2_rn(oacc[nt][2] * inv1, oacc[nt][3] * inv1);
    }
}

// ---------------------------------------------------------------------------
extern "C" void kernel_launch(void* const* d_in, const int* in_sizes, int n_in,
                              void* d_out, int out_size)
{
    const float* x  = (const float*)d_in[0];
    const float* wq = (const float*)d_in[1];
    const float* wk = (const float*)d_in[2];
    const float* wv = (const float*)d_in[3];
    const float* wo = (const float*)d_in[4];
    const float* bo = (const float*)d_in[5];
    float* out = (float*)d_out;

    rope_table_kernel<<<(T_*HALF_D + 255)/256, 256>>>();
    conv_x_kernel<<<(MROWS*NE_/4 + 255)/256, 256>>>(x);

    // Weight transposes into fused fp16 [n][k] buffers (device symbols)
    wtrans_kernel<0><<<dim3(12, 12), 256>>>(wq, 384, 0);
    wtrans_kernel<0><<<dim3(3,  12), 256>>>(wk, 96,  384);
    wtrans_kernel<0><<<dim3(3,  12), 256>>>(wv, 96,  480);
    wtrans_kernel<1><<<dim3(12, 12), 256>>>(wo, 384, 0);

    // Fused QKV projection + RoPE epilogue (N=576)
    gemm_h<0><<<dim3(9, MROWS/128), 256>>>(nullptr, nullptr);

    // V transpose for attention's [d][t] loader
    vtrans_kernel<<<dim3(T_/64, B_*HKV_), 256>>>();

    // Flash attention
    attn_tc<<<dim3(T_/64, B_*HQ_), 128>>>();

    // Output projection + bias
    gemm_h<1><<<dim3(6, MROWS/128), 256>>>(bo, out);
}

// round 10
// speedup vs baseline: 6.8800x; 1.0355x over previous
#include <cuda_runtime.h>
#include <cuda_fp16.h>
#include <math.h>
#include <stdint.h>

#define B_  8
#define T_  2048
#define NE_ 384
#define HQ_ 8
#define HKV_ 2
#define D_  48
#define MROWS (B_*T_)
#define HALF_D 24

// Scratch (device globals; no allocations allowed)
__device__ __half g_xh[(size_t)MROWS*NE_];       // x in fp16
__device__ __half g_wqkvT[(size_t)576*NE_];      // [n][k] fused wq|wk|wv, transposed
__device__ __half g_woT[(size_t)NE_*NE_];        // [n][k] wo transposed
__device__ __half g_q[(size_t)B_*HQ_*T_*D_];     // [B,HQ,T,D] rope'd, pre-scaled by log2e/sqrt(D)
__device__ __half g_k[(size_t)B_*HKV_*T_*D_];    // [B,HKV,T,D] rope'd
__device__ __half g_v[(size_t)B_*HKV_*T_*D_];    // [B,HKV,T,D]
__device__ __half g_vT[(size_t)B_*HKV_*D_*T_];   // [B,HKV,D,T] transposed
__device__ __half g_oh[(size_t)B_*T_*NE_];       // [B,T,NE] attention out fp16
__device__ float  g_cos[T_*HALF_D];
__device__ float  g_sin[T_*HALF_D];

// ---------------------------------------------------------------------------
__device__ __forceinline__ void mma16h(float& d0, float& d1, float& d2, float& d3,
                                       uint32_t a0, uint32_t a1, uint32_t a2, uint32_t a3,
                                       uint32_t b0, uint32_t b1) {
    asm volatile("mma.sync.aligned.m16n8k16.row.col.f32.f16.f16.f32 "
                 "{%0,%1,%2,%3},{%4,%5,%6,%7},{%8,%9},{%0,%1,%2,%3};"
                 : "+f"(d0), "+f"(d1), "+f"(d2), "+f"(d3)
                 : "r"(a0), "r"(a1), "r"(a2), "r"(a3), "r"(b0), "r"(b1));
}
__device__ __forceinline__ void cpa16(uint32_t dst, const void* src) {
    asm volatile("cp.async.cg.shared.global [%0], [%1], 16;" :: "r"(dst), "l"(src) : "memory");
}
__device__ __forceinline__ uint32_t h2bits(__half2 h) {
    return *reinterpret_cast<uint32_t*>(&h);
}
__device__ __forceinline__ float ex2(float x) {
    float y;
    asm("ex2.approx.f32 %0, %1;" : "=f"(y) : "f"(x));
    return y;
}

// ---------------------------------------------------------------------------
__global__ void rope_table_kernel() {
    int idx = blockIdx.x * blockDim.x + threadIdx.x;
    if (idx >= T_ * HALF_D) return;
    int t = idx / HALF_D, p = idx % HALF_D;
    float inv = 1.0f / powf(10000.0f, (2.0f * (float)p) / 48.0f);
    float ang = (float)t * inv;
    g_cos[idx] = (float)cos((double)ang);
    g_sin[idx] = (float)sin((double)ang);
}

// x fp32 -> fp16 (vectorized)
__global__ void conv_x_kernel(const float* __restrict__ x) {
    int i = blockIdx.x * blockDim.x + threadIdx.x;   // float4 index
    if (i >= MROWS * NE_ / 4) return;
    float4 v = ((const float4*)x)[i];
    __half2* dst = (__half2*)g_xh;
    dst[2*i]     = __floats2half2_rn(v.x, v.y);
    dst[2*i + 1] = __floats2half2_rn(v.z, v.w);
}

// W [384][N] fp32 -> fp16 transposed: dst[(n0_out+n)*384 + k] = W[k][n].
template<int DST>
__global__ void wtrans_kernel(const float* __restrict__ W, int N, int n0_out) {
    __shared__ float tile[32][33];
    __half* dst = (DST == 0) ? g_wqkvT : g_woT;
    int k0 = blockIdx.y * 32, n0 = blockIdx.x * 32;
    int tx = threadIdx.x & 31, ty = threadIdx.x >> 5;
    #pragma unroll
    for (int j = 0; j < 4; j++) {
        int r = ty + j * 8;
        tile[r][tx] = W[(size_t)(k0 + r) * N + n0 + tx];
    }
    __syncthreads();
    #pragma unroll
    for (int j = 0; j < 4; j++) {
        int n = ty + j * 8;
        dst[(size_t)(n0_out + n0 + n) * 384 + k0 + tx] = __float2half(tile[tx][n]);
    }
}

// g_v [bh][t][d] -> g_vT [bh][d][t]
__global__ void vtrans_kernel() {
    __shared__ __half tile[64][56];
    int bh = blockIdx.y;
    int t0 = blockIdx.x * 64;
    int tid = threadIdx.x;
    const __half* src = g_v + (size_t)bh * 2048 * 48 + (size_t)t0 * 48;
    #pragma unroll
    for (int i = tid; i < 1536; i += 256) {
        int r = i / 24, c2 = i % 24;
        *(uint32_t*)&tile[r][c2 * 2] = ((const uint32_t*)src)[r * 24 + c2];
    }
    __syncthreads();
    __half* dst = g_vT + (size_t)bh * 48 * 2048 + t0;
    #pragma unroll
    for (int i = tid; i < 1536; i += 256) {
        int d = i / 32, tp = i % 32;
        __half2 hv = __halves2half2(tile[2 * tp][d], tile[2 * tp + 1][d]);
        *(__half2*)&dst[(size_t)d * 2048 + 2 * tp] = hv;
    }
}

// ---------------------------------------------------------------------------
// fp16 tensor-core GEMM, cp.async 3-stage, BK=32, block 128x64, 8 warps 4x2.
// MODE 0: g_xh @ g_wqkvT' (N=576) -> RoPE epilogue -> g_q/g_k/g_v fp16
// MODE 1: g_oh @ g_woT'  (N=384) -> +bias -> fp32 Cout
// ---------------------------------------------------------------------------
template<int MODE>
__global__ __launch_bounds__(256) void gemm_h(
    const float* __restrict__ bias, float* __restrict__ Cout)
{
    __shared__ __half As[3][128][40];
    __shared__ __half Bs[3][64][40];

    const __half* A  = (MODE == 0) ? g_xh    : g_oh;
    const __half* BT = (MODE == 0) ? g_wqkvT : g_woT;

    int tid  = threadIdx.x;
    int lane = tid & 31, wid = tid >> 5;
    int wm = wid & 3, wn = wid >> 2;
    int group = lane >> 2, tid4 = lane & 3;
    int bm = blockIdx.y * 128;
    int bn = blockIdx.x * 64;

    uint32_t as_base = (uint32_t)__cvta_generic_to_shared(&As[0][0][0]);
    uint32_t bs_base = (uint32_t)__cvta_generic_to_shared(&Bs[0][0][0]);

    auto loadTile = [&](int s, int kt) {
        #pragma unroll
        for (int i = tid; i < 512; i += 256) {
            int r = i >> 2, seg = i & 3;
            cpa16(as_base + (uint32_t)(s*10240 + r*80 + seg*16),
                  &A[(size_t)(bm + r) * NE_ + kt*32 + seg*8]);
        }
        {
            int r = tid >> 2, seg = tid & 3;
            cpa16(bs_base + (uint32_t)(s*5120 + r*80 + seg*16),
                  &BT[(size_t)(bn + r) * NE_ + kt*32 + seg*8]);
        }
        asm volatile("cp.async.commit_group;" ::: "memory");
    };

    float acc[2][4][4];
    #pragma unroll
    for (int mt = 0; mt < 2; mt++)
        #pragma unroll
        for (int nt = 0; nt < 4; nt++)
            #pragma unroll
            for (int r = 0; r < 4; r++) acc[mt][nt][r] = 0.f;

    loadTile(0, 0);
    loadTile(1, 1);

    for (int kt = 0; kt < 12; kt++) {
        int s = kt % 3;
        if (kt < 11) asm volatile("cp.async.wait_group 1;" ::: "memory");
        else         asm volatile("cp.async.wait_group 0;" ::: "memory");
        __syncthreads();
        if (kt + 2 < 12) loadTile((kt + 2) % 3, kt + 2);

        #pragma unroll
        for (int ks = 0; ks < 2; ks++) {
            uint32_t af[2][4], bf[4][2];
            #pragma unroll
            for (int mt = 0; mt < 2; mt++) {
                int row = wm * 32 + mt * 16 + group;
                af[mt][0] = *(const uint32_t*)&As[s][row][ks*16 + 2*tid4];
                af[mt][1] = *(const uint32_t*)&As[s][row + 8][ks*16 + 2*tid4];
                af[mt][2] = *(const uint32_t*)&As[s][row][ks*16 + 8 + 2*tid4];
                af[mt][3] = *(const uint32_t*)&As[s][row + 8][ks*16 + 8 + 2*tid4];
            }
            #pragma unroll
            for (int nt = 0; nt < 4; nt++) {
                int nn = wn * 32 + nt * 8 + group;
                bf[nt][0] = *(const uint32_t*)&Bs[s][nn][ks*16 + 2*tid4];
                bf[nt][1] = *(const uint32_t*)&Bs[s][nn][ks*16 + 8 + 2*tid4];
            }
            #pragma unroll
            for (int mt = 0; mt < 2; mt++)
                #pragma unroll
                for (int nt = 0; nt < 4; nt++)
                    mma16h(acc[mt][nt][0], acc[mt][nt][1], acc[mt][nt][2], acc[mt][nt][3],
                           af[mt][0], af[mt][1], af[mt][2], af[mt][3],
                           bf[nt][0], bf[nt][1]);
        }
        __syncthreads();
    }

    // q pre-scale includes log2(e) for exp2-domain softmax
    const float scale = 0.14433756729740643f * 1.4426950408889634f;
    #pragma unroll
    for (int mt = 0; mt < 2; mt++) {
        #pragma unroll
        for (int nt = 0; nt < 4; nt++) {
            int col = bn + wn * 32 + nt * 8 + tid4 * 2;
            #pragma unroll
            for (int half = 0; half < 2; half++) {
                int row = bm + wm * 32 + mt * 16 + group + half * 8;
                float e = acc[mt][nt][half * 2 + 0];
                float o = acc[mt][nt][half * 2 + 1];
                if (MODE == 1) {
                    Cout[(size_t)row * 384 + col]     = e + bias[col];
                    Cout[(size_t)row * 384 + col + 1] = o + bias[col + 1];
                } else {
                    int b = row >> 11, t = row & 2047;
                    if (col < 480) {   // q or k: RoPE
                        int lc = (col < 384) ? col : col - 384;
                        int h = lc / 48, d = lc % 48, p = d >> 1;
                        float cc = g_cos[t * 24 + p], ss = g_sin[t * 24 + p];
                        float re = e * cc - o * ss;
                        float ro = e * ss + o * cc;
                        if (col < 384) {
                            size_t base = (((size_t)b * 8 + h) * 2048 + t) * 48 + d;
                            *(__half2*)&g_q[base] = __floats2half2_rn(re * scale, ro * scale);
                        } else {
                            size_t base = (((size_t)b * 2 + h) * 2048 + t) * 48 + d;
                            *(__half2*)&g_k[base] = __floats2half2_rn(re, ro);
                        }
                    } else {           // v: coalesced [t][d]
                        int lc = col - 480;
                        int h = lc / 48, d = lc % 48;
                        size_t base = (((size_t)b * 2 + h) * 2048 + t) * 48 + d;
                        *(__half2*)&g_v[base] = __floats2half2_rn(e, o);
                    }
                }
            }
        }
    }
}

// ---------------------------------------------------------------------------
// GQA-fused flash attention: one CTA = one kv-head x 32 q-rows x ALL 4 q-heads.
// 256 threads / 8 warps; warp w -> head (w>>1), 16 rows ((w&1)*16 within tile).
// KV smem fill amortized over 4 heads. exp2-domain softmax (ex2.approx).
// Grid: (T/32, B*HKV). One __syncthreads per KV tile.
// ---------------------------------------------------------------------------
__global__ __launch_bounds__(256) void attn_tc() {
    __shared__ __align__(16) __half Ksm[2][64][56];   // [kvrow][d]
    __shared__ __align__(16) __half Vsm[2][48][72];   // [d][kvrow]

    int tid = threadIdx.x, lane = tid & 31, w = tid >> 5;
    int group = lane >> 2, tid4 = lane & 3;
    int bhk = blockIdx.y, b = bhk >> 1, hk = bhk & 1;
    int hg = w >> 1;                  // head within group (0..3)
    int h  = hk * 4 + hg;
    int qt = gridDim.x - 1 - blockIdx.x;    // heavy tiles first
    int m0 = qt * 32;
    int rloc0 = (w & 1) * 16 + group;       // local rows rloc0, rloc0+8 (0..31)

    const __half* Qp = g_q + (((size_t)b * 8 + h) * 2048 + m0) * 48;
    const __half* Kp = g_k + ((size_t)b * 2 + hk) * 2048 * 48;
    const __half* Vp = g_vT + ((size_t)b * 2 + hk) * 48 * 2048;  // [d][t]

    uint32_t ks_base = (uint32_t)__cvta_generic_to_shared(&Ksm[0][0][0]);
    uint32_t vs_base = (uint32_t)__cvta_generic_to_shared(&Vsm[0][0][0]);

    uint32_t qf[3][4];
    #pragma unroll
    for (int ks = 0; ks < 3; ks++) {
        qf[ks][0] = *(const uint32_t*)&Qp[(size_t)rloc0 * 48 + ks*16 + 2*tid4];
        qf[ks][1] = *(const uint32_t*)&Qp[(size_t)(rloc0 + 8) * 48 + ks*16 + 2*tid4];
        qf[ks][2] = *(const uint32_t*)&Qp[(size_t)rloc0 * 48 + ks*16 + 8 + 2*tid4];
        qf[ks][3] = *(const uint32_t*)&Qp[(size_t)(rloc0 + 8) * 48 + ks*16 + 8 + 2*tid4];
    }

    auto loadKV = [&](int s, int tile) {
        const __half* Kt = Kp + (size_t)tile * 64 * 48;
        const __half* Vt = Vp + tile * 64;
        #pragma unroll
        for (int i = tid; i < 384; i += 256) {
            int r = i / 6, seg = i % 6;
            cpa16(ks_base + (uint32_t)((((s*64) + r)*56 + seg*8) * 2),
                  Kt + (size_t)r * 48 + seg * 8);
        }
        #pragma unroll
        for (int i = tid; i < 384; i += 256) {
            int d = i / 8, seg = i % 8;
            cpa16(vs_base + (uint32_t)((((s*48) + d)*72 + seg*8) * 2),
                  Vt + (size_t)d * 2048 + seg * 8);
        }
        asm volatile("cp.async.commit_group;" ::: "memory");
    };

    float oacc[6][4];
    #pragma unroll
    for (int nt = 0; nt < 6; nt++)
        #pragma unroll
        for (int r = 0; r < 4; r++) oacc[nt][r] = 0.f;
    float m0r = -1.0e30f, m1r = -1.0e30f, l0r = 0.f, l1r = 0.f;

    int kend = (m0 + 31) >> 6;     // last KV tile index (inclusive)
    loadKV(0, 0);

    for (int tile = 0; tile <= kend; tile++) {
        int s = tile & 1;
        asm volatile("cp.async.wait_group 0;" ::: "memory");
        __syncthreads();
        if (tile + 1 <= kend) loadKV(s ^ 1, tile + 1);

        float sacc[8][4];
        #pragma unroll
        for (int nt = 0; nt < 8; nt++)
            #pragma unroll
            for (int r = 0; r < 4; r++) sacc[nt][r] = 0.f;
        #pragma unroll
        for (int ks = 0; ks < 3; ks++) {
            #pragma unroll
            for (int nt = 0; nt < 8; nt++) {
                int nn = nt * 8 + group;
                uint32_t b0 = *(const uint32_t*)&Ksm[s][nn][ks*16 + 2*tid4];
                uint32_t b1 = *(const uint32_t*)&Ksm[s][nn][ks*16 + 8 + 2*tid4];
                mma16h(sacc[nt][0], sacc[nt][1], sacc[nt][2], sacc[nt][3],
                       qf[ks][0], qf[ks][1], qf[ks][2], qf[ks][3], b0, b1);
            }
        }

        if (tile == kend) {  // causal mask on final tile (global coords)
            int rg0 = m0 + rloc0, rg1 = rg0 + 8;
            #pragma unroll
            for (int nt = 0; nt < 8; nt++) {
                int cg = tile * 64 + nt * 8 + tid4 * 2;
                if (cg > rg0)     sacc[nt][0] = -1.0e30f;
                if (cg + 1 > rg0) sacc[nt][1] = -1.0e30f;
                if (cg > rg1)     sacc[nt][2] = -1.0e30f;
                if (cg + 1 > rg1) sacc[nt][3] = -1.0e30f;
            }
        }

        float mx0 = -1.0e30f, mx1 = -1.0e30f;
        #pragma unroll
        for (int nt = 0; nt < 8; nt++) {
            mx0 = fmaxf(mx0, fmaxf(sacc[nt][0], sacc[nt][1]));
            mx1 = fmaxf(mx1, fmaxf(sacc[nt][2], sacc[nt][3]));
        }
        mx0 = fmaxf(mx0, __shfl_xor_sync(0xffffffffu, mx0, 1));
        mx0 = fmaxf(mx0, __shfl_xor_sync(0xffffffffu, mx0, 2));
        mx1 = fmaxf(mx1, __shfl_xor_sync(0xffffffffu, mx1, 1));
        mx1 = fmaxf(mx1, __shfl_xor_sync(0xffffffffu, mx1, 2));

        float nm0 = fmaxf(m0r, mx0), nm1 = fmaxf(m1r, mx1);
        float sc0 = ex2(m0r - nm0), sc1 = ex2(m1r - nm1);

        uint32_t ph[8][2];
        float s0 = 0.f, s1 = 0.f;
        #pragma unroll
        for (int nt = 0; nt < 8; nt++) {
            float p0 = ex2(sacc[nt][0] - nm0);
            float p1 = ex2(sacc[nt][1] - nm0);
            float p2 = ex2(sacc[nt][2] - nm1);
            float p3 = ex2(sacc[nt][3] - nm1);
            s0 += p0 + p1; s1 += p2 + p3;
            ph[nt][0] = h2bits(__floats2half2_rn(p0, p1));
            ph[nt][1] = h2bits(__floats2half2_rn(p2, p3));
        }
        s0 += __shfl_xor_sync(0xffffffffu, s0, 1);
        s0 += __shfl_xor_sync(0xffffffffu, s0, 2);
        s1 += __shfl_xor_sync(0xffffffffu, s1, 1);
        s1 += __shfl_xor_sync(0xffffffffu, s1, 2);
        l0r = l0r * sc0 + s0;  m0r = nm0;
        l1r = l1r * sc1 + s1;  m1r = nm1;

        #pragma unroll
        for (int nt = 0; nt < 6; nt++) {
            oacc[nt][0] *= sc0; oacc[nt][1] *= sc0;
            oacc[nt][2] *= sc1; oacc[nt][3] *= sc1;
        }

        #pragma unroll
        for (int kb = 0; kb < 4; kb++) {
            uint32_t a0 = ph[2*kb][0], a1 = ph[2*kb][1];
            uint32_t a2 = ph[2*kb + 1][0], a3 = ph[2*kb + 1][1];
            #pragma unroll
            for (int nt = 0; nt < 6; nt++) {
                int d = nt * 8 + group;
                uint32_t b0 = *(const uint32_t*)&Vsm[s][d][kb * 16 + 2 * tid4];
                uint32_t b1 = *(const uint32_t*)&Vsm[s][d][kb * 16 + 8 + 2 * tid4];
                mma16h(oacc[nt][0], oacc[nt][1], oacc[nt][2], oacc[nt][3],
                       a0, a1, a2, a3, b0, b1);
            }
        }
    }

    float inv0 = 1.0f / l0r, inv1 = 1.0f / l1r;
    __half* Op = g_oh + ((size_t)b * 2048 + m0 + rloc0) * 384 + h * 48;
    #pragma unroll
    for (int nt = 0; nt < 6; nt++) {
        int d = nt * 8 + 2 * tid4;
        *(__half2*)&Op[d] =
            __floats2half2_rn(oacc[nt][0] * inv0, oacc[nt][1] * inv0);
        *(__half2*)&Op[(size_t)8 * 384 + d] =
            __floats2half2_rn(oacc[nt][2] * inv1, oacc[nt][3] * inv1);
    }
}

// ---------------------------------------------------------------------------
extern "C" void kernel_launch(void* const* d_in, const int* in_sizes, int n_in,
                              void* d_out, int out_size)
{
    const float* x  = (const float*)d_in[0];
    const float* wq = (const float*)d_in[1];
    const float* wk = (const float*)d_in[2];
    const float* wv = (const float*)d_in[3];
    const float* wo = (const float*)d_in[4];
    const float* bo = (const float*)d_in[5];
    float* out = (float*)d_out;

    rope_table_kernel<<<(T_*HALF_D + 255)/256, 256>>>();
    conv_x_kernel<<<(MROWS*NE_/4 + 255)/256, 256>>>(x);

    wtrans_kernel<0><<<dim3(12, 12), 256>>>(wq, 384, 0);
    wtrans_kernel<0><<<dim3(3,  12), 256>>>(wk, 96,  384);
    wtrans_kernel<0><<<dim3(3,  12), 256>>>(wv, 96,  480);
    wtrans_kernel<1><<<dim3(12, 12), 256>>>(wo, 384, 0);

    // Fused QKV projection + RoPE epilogue (N=576)
    gemm_h<0><<<dim3(9, MROWS/128), 256>>>(nullptr, nullptr);

    // V transpose for attention's [d][t] loader
    vtrans_kernel<<<dim3(T_/64, B_*HKV_), 256>>>();

    // GQA-fused flash attention (4 heads per CTA)
    attn_tc<<<dim3(T_/32, B_*HKV_), 256>>>();

    // Output projection + bias
    gemm_h<1><<<dim3(6, MROWS/128), 256>>>(bo, out);
}

// round 11
// speedup vs baseline: 7.0699x; 1.0276x over previous
#include <cuda_runtime.h>
#include <cuda_fp16.h>
#include <math.h>
#include <stdint.h>

#define B_  8
#define T_  2048
#define NE_ 384
#define HQ_ 8
#define HKV_ 2
#define D_  48
#define MROWS (B_*T_)
#define HALF_D 24
#define KT_ 96     // attention KV tile rows

// Scratch (device globals; no allocations allowed)
__device__ __half g_xh[(size_t)MROWS*NE_];       // x in fp16
__device__ __half g_wqkvT[(size_t)576*NE_];      // [n][k] fused wq|wk|wv, transposed
__device__ __half g_woT[(size_t)NE_*NE_];        // [n][k] wo transposed
__device__ __half g_q[(size_t)B_*HQ_*T_*D_];     // [B,HQ,T,D] rope'd, scaled by log2e/sqrt(D)
__device__ __half g_k[(size_t)B_*HKV_*T_*D_];    // [B,HKV,T,D] rope'd
__device__ __half g_v[(size_t)B_*HKV_*T_*D_];    // [B,HKV,T,D]
__device__ __half g_vT[(size_t)B_*HKV_*D_*T_];   // [B,HKV,D,T] transposed
__device__ __half g_oh[(size_t)B_*T_*NE_];       // [B,T,NE] attention out fp16
__device__ float  g_cos[T_*HALF_D];
__device__ float  g_sin[T_*HALF_D];

// ---------------------------------------------------------------------------
__device__ __forceinline__ void mma16h(float& d0, float& d1, float& d2, float& d3,
                                       uint32_t a0, uint32_t a1, uint32_t a2, uint32_t a3,
                                       uint32_t b0, uint32_t b1) {
    asm volatile("mma.sync.aligned.m16n8k16.row.col.f32.f16.f16.f32 "
                 "{%0,%1,%2,%3},{%4,%5,%6,%7},{%8,%9},{%0,%1,%2,%3};"
                 : "+f"(d0), "+f"(d1), "+f"(d2), "+f"(d3)
                 : "r"(a0), "r"(a1), "r"(a2), "r"(a3), "r"(b0), "r"(b1));
}
__device__ __forceinline__ void cpa16(uint32_t dst, const void* src) {
    asm volatile("cp.async.cg.shared.global [%0], [%1], 16;" :: "r"(dst), "l"(src) : "memory");
}
__device__ __forceinline__ uint32_t h2bits(__half2 h) {
    return *reinterpret_cast<uint32_t*>(&h);
}
__device__ __forceinline__ float ex2(float x) {
    float y;
    asm("ex2.approx.f32 %0, %1;" : "=f"(y) : "f"(x));
    return y;
}

// ---------------------------------------------------------------------------
__global__ void rope_table_kernel() {
    int idx = blockIdx.x * blockDim.x + threadIdx.x;
    if (idx >= T_ * HALF_D) return;
    int t = idx / HALF_D, p = idx % HALF_D;
    float inv = 1.0f / powf(10000.0f, (2.0f * (float)p) / 48.0f);
    float ang = (float)t * inv;
    g_cos[idx] = (float)cos((double)ang);
    g_sin[idx] = (float)sin((double)ang);
}

// x fp32 -> fp16 (vectorized)
__global__ void conv_x_kernel(const float* __restrict__ x) {
    int i = blockIdx.x * blockDim.x + threadIdx.x;
    if (i >= MROWS * NE_ / 4) return;
    float4 v = ((const float4*)x)[i];
    __half2* dst = (__half2*)g_xh;
    dst[2*i]     = __floats2half2_rn(v.x, v.y);
    dst[2*i + 1] = __floats2half2_rn(v.z, v.w);
}

// All 4 weight transposes in one launch. blockIdx.x in [0,30):
//  [0,12) wq->wqkvT@0, [12,15) wk->wqkvT@384, [15,18) wv->wqkvT@480, [18,30) wo->woT
__global__ void wtrans_all_kernel(const float* __restrict__ wq, const float* __restrict__ wk,
                                  const float* __restrict__ wv, const float* __restrict__ wo) {
    __shared__ float tile[32][33];
    int bx = blockIdx.x;
    const float* W; __half* dst; int N, n0_out, nb;
    if (bx < 12)      { W = wq; dst = g_wqkvT; N = 384; n0_out = 0;   nb = bx; }
    else if (bx < 15) { W = wk; dst = g_wqkvT; N = 96;  n0_out = 384; nb = bx - 12; }
    else if (bx < 18) { W = wv; dst = g_wqkvT; N = 96;  n0_out = 480; nb = bx - 15; }
    else              { W = wo; dst = g_woT;   N = 384; n0_out = 0;   nb = bx - 18; }
    int k0 = blockIdx.y * 32, n0 = nb * 32;
    int tx = threadIdx.x & 31, ty = threadIdx.x >> 5;
    #pragma unroll
    for (int j = 0; j < 4; j++) {
        int r = ty + j * 8;
        tile[r][tx] = W[(size_t)(k0 + r) * N + n0 + tx];
    }
    __syncthreads();
    #pragma unroll
    for (int j = 0; j < 4; j++) {
        int n = ty + j * 8;
        dst[(size_t)(n0_out + n0 + n) * 384 + k0 + tx] = __float2half(tile[tx][n]);
    }
}

// g_v [bh][t][d] -> g_vT [bh][d][t]
__global__ void vtrans_kernel() {
    __shared__ __half tile[64][56];
    int bh = blockIdx.y;
    int t0 = blockIdx.x * 64;
    int tid = threadIdx.x;
    const __half* src = g_v + (size_t)bh * 2048 * 48 + (size_t)t0 * 48;
    #pragma unroll
    for (int i = tid; i < 1536; i += 256) {
        int r = i / 24, c2 = i % 24;
        *(uint32_t*)&tile[r][c2 * 2] = ((const uint32_t*)src)[r * 24 + c2];
    }
    __syncthreads();
    __half* dst = g_vT + (size_t)bh * 48 * 2048 + t0;
    #pragma unroll
    for (int i = tid; i < 1536; i += 256) {
        int d = i / 32, tp = i % 32;
        __half2 hv = __halves2half2(tile[2 * tp][d], tile[2 * tp + 1][d]);
        *(__half2*)&dst[(size_t)d * 2048 + 2 * tp] = hv;
    }
}

// ---------------------------------------------------------------------------
// fp16 tensor-core GEMM, cp.async 3-stage, BK=32, block 128x64, 8 warps 4x2.
// Both epilogues stage through smem for fully-coalesced global stores.
// MODE 0: g_xh @ g_wqkvT' (N=576) -> RoPE -> g_q/g_k/g_v fp16
// MODE 1: g_oh @ g_woT'  (N=384) -> +bias -> fp32 Cout
// ---------------------------------------------------------------------------
template<int MODE>
__global__ __launch_bounds__(256) void gemm_h(
    const float* __restrict__ bias, float* __restrict__ Cout)
{
    __shared__ __align__(16) char SMEM[46080];
    // As: 3 stages of [128][40] halves (10240 B each); Bs: 3 of [64][40] (5120 B)
    __half* Asm = (__half*)SMEM;              // As[s][r][c] = Asm[s*5120 + r*40 + c]
    __half* Bsm = (__half*)(SMEM + 30720);    // Bs[s][r][c] = Bsm[s*2560 + r*40 + c]

    const __half* A  = (MODE == 0) ? g_xh    : g_oh;
    const __half* BT = (MODE == 0) ? g_wqkvT : g_woT;

    int tid  = threadIdx.x;
    int lane = tid & 31, wid = tid >> 5;
    int wm = wid & 3, wn = wid >> 2;
    int group = lane >> 2, tid4 = lane & 3;
    int bm = blockIdx.y * 128;
    int bn = blockIdx.x * 64;

    uint32_t as_base = (uint32_t)__cvta_generic_to_shared(Asm);
    uint32_t bs_base = (uint32_t)__cvta_generic_to_shared(Bsm);

    auto loadTile = [&](int s, int kt) {
        #pragma unroll
        for (int i = tid; i < 512; i += 256) {
            int r = i >> 2, seg = i & 3;
            cpa16(as_base + (uint32_t)(s*10240 + r*80 + seg*16),
                  &A[(size_t)(bm + r) * NE_ + kt*32 + seg*8]);
        }
        {
            int r = tid >> 2, seg = tid & 3;
            cpa16(bs_base + (uint32_t)(s*5120 + r*80 + seg*16),
                  &BT[(size_t)(bn + r) * NE_ + kt*32 + seg*8]);
        }
        asm volatile("cp.async.commit_group;" ::: "memory");
    };

    float acc[2][4][4];
    #pragma unroll
    for (int mt = 0; mt < 2; mt++)
        #pragma unroll
        for (int nt = 0; nt < 4; nt++)
            #pragma unroll
            for (int r = 0; r < 4; r++) acc[mt][nt][r] = 0.f;

    loadTile(0, 0);
    loadTile(1, 1);

    for (int kt = 0; kt < 12; kt++) {
        int s = kt % 3;
        if (kt < 11) asm volatile("cp.async.wait_group 1;" ::: "memory");
        else         asm volatile("cp.async.wait_group 0;" ::: "memory");
        __syncthreads();
        if (kt + 2 < 12) loadTile((kt + 2) % 3, kt + 2);

        #pragma unroll
        for (int ks = 0; ks < 2; ks++) {
            uint32_t af[2][4], bf[4][2];
            #pragma unroll
            for (int mt = 0; mt < 2; mt++) {
                int row = wm * 32 + mt * 16 + group;
                af[mt][0] = *(const uint32_t*)&Asm[s*5120 + row*40 + ks*16 + 2*tid4];
                af[mt][1] = *(const uint32_t*)&Asm[s*5120 + (row+8)*40 + ks*16 + 2*tid4];
                af[mt][2] = *(const uint32_t*)&Asm[s*5120 + row*40 + ks*16 + 8 + 2*tid4];
                af[mt][3] = *(const uint32_t*)&Asm[s*5120 + (row+8)*40 + ks*16 + 8 + 2*tid4];
            }
            #pragma unroll
            for (int nt = 0; nt < 4; nt++) {
                int nn = wn * 32 + nt * 8 + group;
                bf[nt][0] = *(const uint32_t*)&Bsm[s*2560 + nn*40 + ks*16 + 2*tid4];
                bf[nt][1] = *(const uint32_t*)&Bsm[s*2560 + nn*40 + ks*16 + 8 + 2*tid4];
            }
            #pragma unroll
            for (int mt = 0; mt < 2; mt++)
                #pragma unroll
                for (int nt = 0; nt < 4; nt++)
                    mma16h(acc[mt][nt][0], acc[mt][nt][1], acc[mt][nt][2], acc[mt][nt][3],
                           af[mt][0], af[mt][1], af[mt][2], af[mt][3],
                           bf[nt][0], bf[nt][1]);
        }
        __syncthreads();
    }
    // final loop iteration ended with __syncthreads -> smem reusable

    if (MODE == 1) {
        // Stage fp32 C tile [128][66] (pad 66 kills STS bank conflicts), coalesced copy.
        float* Ct = (float*)SMEM;   // 128*66*4 = 33792 B
        #pragma unroll
        for (int mt = 0; mt < 2; mt++)
            #pragma unroll
            for (int nt = 0; nt < 4; nt++) {
                int cl = wn * 32 + nt * 8 + tid4 * 2;
                float b0 = bias[bn + cl], b1 = bias[bn + cl + 1];
                #pragma unroll
                for (int half = 0; half < 2; half++) {
                    int rL = wm * 32 + mt * 16 + group + half * 8;
                    *(float2*)&Ct[rL * 66 + cl] =
                        make_float2(acc[mt][nt][half*2+0] + b0, acc[mt][nt][half*2+1] + b1);
                }
            }
        __syncthreads();
        #pragma unroll
        for (int i = tid; i < 4096; i += 256) {
            int r = i >> 5, c2 = (i & 31) * 2;
            float2 v = *(float2*)&Ct[r * 66 + c2];
            *(float2*)&Cout[(size_t)(bm + r) * 384 + bn + c2] = v;
        }
    } else {
        // RoPE in regs -> fp16 tile [128][68] -> warp-per-row coalesced scatter.
        __half* Ht = (__half*)SMEM;  // 128*68*2 = 17408 B
        const float scale = 0.14433756729740643f * 1.4426950408889634f; // /sqrt(48)*log2e
        #pragma unroll
        for (int mt = 0; mt < 2; mt++)
            #pragma unroll
            for (int nt = 0; nt < 4; nt++) {
                int cl = wn * 32 + nt * 8 + tid4 * 2;
                int gc = bn + cl;
                #pragma unroll
                for (int half = 0; half < 2; half++) {
                    int rL = wm * 32 + mt * 16 + group + half * 8;
                    float e = acc[mt][nt][half*2+0];
                    float o = acc[mt][nt][half*2+1];
                    __half2 hv;
                    if (gc < 480) {
                        int t = (bm + rL) & 2047;
                        int lc = (gc < 384) ? gc : gc - 384;
                        int p = (lc % 48) >> 1;
                        float cc = g_cos[t*24 + p], ss = g_sin[t*24 + p];
                        float re = e*cc - o*ss, ro = e*ss + o*cc;
                        hv = (gc < 384) ? __floats2half2_rn(re*scale, ro*scale)
                                        : __floats2half2_rn(re, ro);
                    } else {
                        hv = __floats2half2_rn(e, o);
                    }
                    *(__half2*)&Ht[rL * 68 + cl] = hv;
                }
            }
        __syncthreads();
        int lane2 = lane * 2;
        int gc = bn + lane2;
        int region = (gc < 384) ? 0 : ((gc < 480) ? 1 : 2);
        int lc = gc - ((region == 0) ? 0 : ((region == 1) ? 384 : 480));
        int hh = lc / 48, dd = lc % 48;
        __half* dstbuf = (region == 0) ? g_q : ((region == 1) ? g_k : g_v);
        int nheads = (region == 0) ? 8 : 2;
        #pragma unroll
        for (int it = 0; it < 16; it++) {
            int rL = wid * 16 + it;
            int row = bm + rL;
            int b = row >> 11, t = row & 2047;
            __half2 hv = *(__half2*)&Ht[rL * 68 + lane2];
            size_t addr = (((size_t)b * nheads + hh) * 2048 + t) * 48 + dd;
            *(__half2*)&dstbuf[addr] = hv;
        }
    }
}

// ---------------------------------------------------------------------------
// GQA-fused flash attention, KV tile 96. One CTA = 1 kv-head x 32 q-rows x 4 heads.
// 256 threads / 8 warps; warp w -> head (w>>1), rows (w&1)*16. exp2 softmax.
// Grid: (T/32, B*HKV). One __syncthreads per KV tile.
// ---------------------------------------------------------------------------
__global__ __launch_bounds__(256) void attn_tc() {
    __shared__ __align__(16) __half Ksm[2][KT_][56];    // [kvrow][d]   21504 B
    __shared__ __align__(16) __half Vsm[2][48][KT_+8];  // [d][kvrow]   19968 B

    int tid = threadIdx.x, lane = tid & 31, w = tid >> 5;
    int group = lane >> 2, tid4 = lane & 3;
    int bhk = blockIdx.y, b = bhk >> 1, hk = bhk & 1;
    int h  = hk * 4 + (w >> 1);
    int qt = gridDim.x - 1 - blockIdx.x;    // heavy tiles first
    int m0 = qt * 32;
    int rloc0 = (w & 1) * 16 + group;

    const __half* Qp = g_q + (((size_t)b * 8 + h) * 2048 + m0) * 48;
    const __half* Kp = g_k + ((size_t)b * 2 + hk) * 2048 * 48;
    const __half* Vp = g_vT + ((size_t)b * 2 + hk) * 48 * 2048;  // [d][t]

    uint32_t ks_base = (uint32_t)__cvta_generic_to_shared(&Ksm[0][0][0]);
    uint32_t vs_base = (uint32_t)__cvta_generic_to_shared(&Vsm[0][0][0]);

    uint32_t qf[3][4];
    #pragma unroll
    for (int ks = 0; ks < 3; ks++) {
        qf[ks][0] = *(const uint32_t*)&Qp[(size_t)rloc0 * 48 + ks*16 + 2*tid4];
        qf[ks][1] = *(const uint32_t*)&Qp[(size_t)(rloc0 + 8) * 48 + ks*16 + 2*tid4];
        qf[ks][2] = *(const uint32_t*)&Qp[(size_t)rloc0 * 48 + ks*16 + 8 + 2*tid4];
        qf[ks][3] = *(const uint32_t*)&Qp[(size_t)(rloc0 + 8) * 48 + ks*16 + 8 + 2*tid4];
    }

    auto loadKV = [&](int s, int tile) {
        const __half* Kt = Kp + (size_t)tile * KT_ * 48;
        int tbase = tile * KT_;
        #pragma unroll
        for (int i = tid; i < KT_*6; i += 256) {          // K: 96 rows x 6 segs
            int r = i / 6, seg = i % 6;
            if (tbase + r < 2048)
                cpa16(ks_base + (uint32_t)(((s*KT_ + r)*56 + seg*8) * 2),
                      Kt + (size_t)r * 48 + seg * 8);
        }
        #pragma unroll
        for (int i = tid; i < 48*(KT_/8); i += 256) {     // V: 48 d x 12 segs
            int d = i / 12, seg = i % 12;
            if (tbase + seg*8 < 2048)
                cpa16(vs_base + (uint32_t)(((s*48 + d)*(KT_+8) + seg*8) * 2),
                      Vp + (size_t)d * 2048 + tbase + seg * 8);
        }
        asm volatile("cp.async.commit_group;" ::: "memory");
    };

    float oacc[6][4];
    #pragma unroll
    for (int nt = 0; nt < 6; nt++)
        #pragma unroll
        for (int r = 0; r < 4; r++) oacc[nt][r] = 0.f;
    float m0r = -1.0e30f, m1r = -1.0e30f, l0r = 0.f, l1r = 0.f;

    int kend = (m0 + 31) / KT_;    // last KV tile (inclusive)
    loadKV(0, 0);

    for (int tile = 0; tile <= kend; tile++) {
        int s = tile & 1;
        asm volatile("cp.async.wait_group 0;" ::: "memory");
        __syncthreads();
        if (tile + 1 <= kend) loadKV(s ^ 1, tile + 1);

        float sacc[12][4];
        #pragma unroll
        for (int nt = 0; nt < 12; nt++)
            #pragma unroll
            for (int r = 0; r < 4; r++) sacc[nt][r] = 0.f;
        #pragma unroll
        for (int ks = 0; ks < 3; ks++) {
            #pragma unroll
            for (int nt = 0; nt < 12; nt++) {
                int nn = nt * 8 + group;
                uint32_t b0 = *(const uint32_t*)&Ksm[s][nn][ks*16 + 2*tid4];
                uint32_t b1 = *(const uint32_t*)&Ksm[s][nn][ks*16 + 8 + 2*tid4];
                mma16h(sacc[nt][0], sacc[nt][1], sacc[nt][2], sacc[nt][3],
                       qf[ks][0], qf[ks][1], qf[ks][2], qf[ks][3], b0, b1);
            }
        }

        if (tile == kend) {  // causal mask on final tile (global coords)
            int rg0 = m0 + rloc0, rg1 = rg0 + 8;
            #pragma unroll
            for (int nt = 0; nt < 12; nt++) {
                int cg = tile * KT_ + nt * 8 + tid4 * 2;
                if (cg > rg0)     sacc[nt][0] = -1.0e30f;
                if (cg + 1 > rg0) sacc[nt][1] = -1.0e30f;
                if (cg > rg1)     sacc[nt][2] = -1.0e30f;
                if (cg + 1 > rg1) sacc[nt][3] = -1.0e30f;
            }
        }

        float mx0 = -1.0e30f, mx1 = -1.0e30f;
        #pragma unroll
        for (int nt = 0; nt < 12; nt++) {
            mx0 = fmaxf(mx0, fmaxf(sacc[nt][0], sacc[nt][1]));
            mx1 = fmaxf(mx1, fmaxf(sacc[nt][2], sacc[nt][3]));
        }
        mx0 = fmaxf(mx0, __shfl_xor_sync(0xffffffffu, mx0, 1));
        mx0 = fmaxf(mx0, __shfl_xor_sync(0xffffffffu, mx0, 2));
        mx1 = fmaxf(mx1, __shfl_xor_sync(0xffffffffu, mx1, 1));
        mx1 = fmaxf(mx1, __shfl_xor_sync(0xffffffffu, mx1, 2));

        float nm0 = fmaxf(m0r, mx0), nm1 = fmaxf(m1r, mx1);
        float sc0 = ex2(m0r - nm0), sc1 = ex2(m1r - nm1);

        uint32_t ph[12][2];
        float s0 = 0.f, s1 = 0.f;
        #pragma unroll
        for (int nt = 0; nt < 12; nt++) {
            float p0 = ex2(sacc[nt][0] - nm0);
            float p1 = ex2(sacc[nt][1] - nm0);
            float p2 = ex2(sacc[nt][2] - nm1);
            float p3 = ex2(sacc[nt][3] - nm1);
            s0 += p0 + p1; s1 += p2 + p3;
            ph[nt][0] = h2bits(__floats2half2_rn(p0, p1));
            ph[nt][1] = h2bits(__floats2half2_rn(p2, p3));
        }
        s0 += __shfl_xor_sync(0xffffffffu, s0, 1);
        s0 += __shfl_xor_sync(0xffffffffu, s0, 2);
        s1 += __shfl_xor_sync(0xffffffffu, s1, 1);
        s1 += __shfl_xor_sync(0xffffffffu, s1, 2);
        l0r = l0r * sc0 + s0;  m0r = nm0;
        l1r = l1r * sc1 + s1;  m1r = nm1;

        #pragma unroll
        for (int nt = 0; nt < 6; nt++) {
            oacc[nt][0] *= sc0; oacc[nt][1] *= sc0;
            oacc[nt][2] *= sc1; oacc[nt][3] *= sc1;
        }

        #pragma unroll
        for (int kb = 0; kb < 6; kb++) {
            uint32_t a0 = ph[2*kb][0], a1 = ph[2*kb][1];
            uint32_t a2 = ph[2*kb + 1][0], a3 = ph[2*kb + 1][1];
            #pragma unroll
            for (int nt = 0; nt < 6; nt++) {
                int d = nt * 8 + group;
                uint32_t b0 = *(const uint32_t*)&Vsm[s][d][kb * 16 + 2 * tid4];
                uint32_t b1 = *(const uint32_t*)&Vsm[s][d][kb * 16 + 8 + 2 * tid4];
                mma16h(oacc[nt][0], oacc[nt][1], oacc[nt][2], oacc[nt][3],
                       a0, a1, a2, a3, b0, b1);
            }
        }
    }

    float inv0 = 1.0f / l0r, inv1 = 1.0f / l1r;
    __half* Op = g_oh + ((size_t)b * 2048 + m0 + rloc0) * 384 + h * 48;
    #pragma unroll
    for (int nt = 0; nt < 6; nt++) {
        int d = nt * 8 + 2 * tid4;
        *(__half2*)&Op[d] =
            __floats2half2_rn(oacc[nt][0] * inv0, oacc[nt][1] * inv0);
        *(__half2*)&Op[(size_t)8 * 384 + d] =
            __floats2half2_rn(oacc[nt][2] * inv1, oacc[nt][3] * inv1);
    }
}

// ---------------------------------------------------------------------------
extern "C" void kernel_launch(void* const* d_in, const int* in_sizes, int n_in,
                              void* d_out, int out_size)
{
    const float* x  = (const float*)d_in[0];
    const float* wq = (const float*)d_in[1];
    const float* wk = (const float*)d_in[2];
    const float* wv = (const float*)d_in[3];
    const float* wo = (const float*)d_in[4];
    const float* bo = (const float*)d_in[5];
    float* out = (float*)d_out;

    rope_table_kernel<<<(T_*HALF_D + 255)/256, 256>>>();
    conv_x_kernel<<<(MROWS*NE_/4 + 255)/256, 256>>>(x);
    wtrans_all_kernel<<<dim3(30, 12), 256>>>(wq, wk, wv, wo);

    // Fused QKV projection + RoPE epilogue (N=576)
    gemm_h<0><<<dim3(9, MROWS/128), 256>>>(nullptr, nullptr);

    // V transpose for attention's [d][t] loader
    vtrans_kernel<<<dim3(T_/64, B_*HKV_), 256>>>();

    // GQA-fused flash attention (4 heads per CTA, KV tile 96)
    attn_tc<<<dim3(T_/32, B_*HKV_), 256>>>();

    // Output projection + bias
    gemm_h<1><<<dim3(6, MROWS/128), 256>>>(bo, out);
}